// round 6
// baseline (speedup 1.0000x reference)
#include <cuda_runtime.h>
#include <cuda_bf16.h>
#include <cfloat>
#include <cstdint>

#define N_NODES 50000
#define IN_DIM  1024
#define E_EDGES 100000
#define NUM_REL 40
#define HEADS   4
#define OUT_DIM 200
#define HID     800
#define BATCH   8192
#define NEG_SLOPE 0.2f

#define BM 128
#define BN 64
#define BK 32
#define NCHUNK (IN_DIM / BK)            // 32
#define NT_M ((N_NODES + BM - 1) / BM)  // 391
#define NT_N 13                         // ceil(800/64)
#define PAD_N (NT_N * BN)               // 832

// smem layout (bytes from dynamic base); padded row stride 80B (40 bf16)
#define A_STRIDE 80
#define A_VER_SZ (128 * A_STRIDE)       // 10240
#define B_VER_SZ (64 * A_STRIDE)        // 5120
#define SA_OFF(buf, ver) ((buf) * (2 * A_VER_SZ) + (ver) * A_VER_SZ)
#define SB_OFF(buf, ver) (4 * A_VER_SZ + (buf) * (2 * B_VER_SZ) + (ver) * B_VER_SZ)
#define SM_TOT (4 * A_VER_SZ + 4 * B_VER_SZ)   // 61440

// ---------------- scratch (device globals) ----------------
__device__ __align__(16) float g_h  [(size_t)N_NODES * HID];
__device__ __align__(16) float g_out[(size_t)N_NODES * HID];
__device__ __align__(16) __nv_bfloat16 g_Ah[(size_t)N_NODES * IN_DIM];
__device__ __align__(16) __nv_bfloat16 g_Al[(size_t)N_NODES * IN_DIM];
__device__ __align__(16) __nv_bfloat16 g_Bh[(size_t)PAD_N * IN_DIM];  // B^T, K-major
__device__ __align__(16) __nv_bfloat16 g_Bl[(size_t)PAD_N * IN_DIM];
__device__ __align__(16) float g_csrc[IN_DIM * HEADS];   // (W @ a_src per head) [k][h]
__device__ __align__(16) float g_cdst[IN_DIM * HEADS];
__device__ __align__(16) float g_ssrc  [N_NODES * HEADS];
__device__ __align__(16) float g_sdst  [N_NODES * HEADS];
__device__ float g_rlog  [NUM_REL * HEADS];
__device__ __align__(16) float g_denom [N_NODES * HEADS];
__device__ __align__(16) float g_elog  [E_EDGES * HEADS];
__device__ int   g_cnt   [N_NODES];
__device__ int   g_rowptr[N_NODES + 1];
__device__ int   g_cursor[N_NODES];
__device__ int   g_csre  [E_EDGES];
__device__ int   g_is64;

// ---------------- helpers ----------------
__device__ __forceinline__ int load_idx(const void* p, int i) {
    if (g_is64) return (int)((const long long*)p)[i];
    return ((const int*)p)[i];
}
__device__ __forceinline__ float warp_reduce(float v) {
    #pragma unroll
    for (int o = 16; o > 0; o >>= 1) v += __shfl_down_sync(0xffffffffu, v, o);
    return v;
}
__device__ __forceinline__ uint32_t smem_u32(const void* p) {
    uint32_t a;
    asm("{ .reg .u64 t; cvta.to.shared.u64 t, %1; cvt.u32.u64 %0, t; }" : "=r"(a) : "l"(p));
    return a;
}
__device__ __forceinline__ void cp_async16(uint32_t s, const void* g) {
    asm volatile("cp.async.cg.shared.global [%0], [%1], 16;" :: "r"(s), "l"(g));
}
__device__ __forceinline__ void cp_commit() {
    asm volatile("cp.async.commit_group;" ::: "memory");
}
template<int NN> __device__ __forceinline__ void cp_wait() {
    asm volatile("cp.async.wait_group %0;" :: "n"(NN) : "memory");
}
__device__ __forceinline__ void ldm_x4(uint32_t* r, uint32_t addr) {
    asm volatile("ldmatrix.sync.aligned.m8n8.x4.shared.b16 {%0,%1,%2,%3}, [%4];"
                 : "=r"(r[0]), "=r"(r[1]), "=r"(r[2]), "=r"(r[3]) : "r"(addr));
}
__device__ __forceinline__ void mma16816(float* d, const uint32_t* a, const uint32_t* b) {
    asm volatile(
        "mma.sync.aligned.m16n8k16.row.col.f32.bf16.bf16.f32 "
        "{%0,%1,%2,%3}, {%4,%5,%6,%7}, {%8,%9}, {%0,%1,%2,%3};"
        : "+f"(d[0]), "+f"(d[1]), "+f"(d[2]), "+f"(d[3])
        : "r"(a[0]), "r"(a[1]), "r"(a[2]), "r"(a[3]), "r"(b[0]), "r"(b[1]));
}

// ---------------- 0) dtype detection ----------------
__global__ void detect_dtype_kernel(const void* edge_index) {
    if (threadIdx.x == 0 && blockIdx.x == 0) {
        const long long* p = (const long long*)edge_index;
        int ok = 1;
        for (int i = 0; i < 64; i++) {
            long long v = p[i];
            if (v < 0 || v >= N_NODES) { ok = 0; break; }
        }
        g_is64 = ok;
    }
}

// ---------------- 1) c vectors: c_src[k][h] = sum_d W[k, h*200+d] * a_src[h][d] -----
__global__ void cvec_kernel(const float* __restrict__ Wm,
                            const float* __restrict__ a_src,
                            const float* __restrict__ a_dst) {
    int wid  = (blockIdx.x * blockDim.x + threadIdx.x) >> 5;
    int lane = threadIdx.x & 31;
    if (wid >= IN_DIM * HEADS) return;
    int k = wid >> 2, h = wid & 3;
    const float* wrow = Wm + (size_t)k * HID + h * OUT_DIM;
    const float* as = a_src + h * OUT_DIM;
    const float* ad = a_dst + h * OUT_DIM;
    float cs = 0.f, cd = 0.f;
    for (int d = lane; d < OUT_DIM; d += 32) {
        float w = wrow[d];
        cs = fmaf(w, as[d], cs);
        cd = fmaf(w, ad[d], cd);
    }
    cs = warp_reduce(cs);
    cd = warp_reduce(cd);
    if (lane == 0) { g_csrc[k * 4 + h] = cs; g_cdst[k * 4 + h] = cd; }
}

// ---------------- 2a) split A into bf16 hi/lo + fused s_src/s_dst ----------------
// one warp per node row
__global__ void __launch_bounds__(256) split_a_kernel(const float* __restrict__ A) {
    int gw   = (blockIdx.x * blockDim.x + threadIdx.x) >> 5;
    int lane = threadIdx.x & 31;
    if (gw >= N_NODES) return;
    const float4* arow = (const float4*)(A + (size_t)gw * IN_DIM);
    __nv_bfloat162* ph = (__nv_bfloat162*)(g_Ah + (size_t)gw * IN_DIM);
    __nv_bfloat162* pl = (__nv_bfloat162*)(g_Al + (size_t)gw * IN_DIM);
    const float4* cs = (const float4*)g_csrc;
    const float4* cd = (const float4*)g_cdst;
    float ss[4] = {0.f, 0.f, 0.f, 0.f};
    float sd[4] = {0.f, 0.f, 0.f, 0.f};
    #pragma unroll
    for (int it = 0; it < 8; it++) {
        int k4 = lane + it * 32;             // float4 index within row
        float4 a = arow[k4];
        float av[4] = {a.x, a.y, a.z, a.w};
        #pragma unroll
        for (int q = 0; q < 4; q++) {
            int k = k4 * 4 + q;
            float4 c1 = cs[k], c2 = cd[k];
            ss[0] = fmaf(av[q], c1.x, ss[0]); ss[1] = fmaf(av[q], c1.y, ss[1]);
            ss[2] = fmaf(av[q], c1.z, ss[2]); ss[3] = fmaf(av[q], c1.w, ss[3]);
            sd[0] = fmaf(av[q], c2.x, sd[0]); sd[1] = fmaf(av[q], c2.y, sd[1]);
            sd[2] = fmaf(av[q], c2.z, sd[2]); sd[3] = fmaf(av[q], c2.w, sd[3]);
        }
        __nv_bfloat16 hx = __float2bfloat16(a.x), hy = __float2bfloat16(a.y);
        __nv_bfloat16 hz = __float2bfloat16(a.z), hw = __float2bfloat16(a.w);
        __nv_bfloat16 lx = __float2bfloat16(a.x - __bfloat162float(hx));
        __nv_bfloat16 ly = __float2bfloat16(a.y - __bfloat162float(hy));
        __nv_bfloat16 lz = __float2bfloat16(a.z - __bfloat162float(hz));
        __nv_bfloat16 lw = __float2bfloat16(a.w - __bfloat162float(hw));
        ph[k4 * 2]     = __nv_bfloat162(hx, hy);
        ph[k4 * 2 + 1] = __nv_bfloat162(hz, hw);
        pl[k4 * 2]     = __nv_bfloat162(lx, ly);
        pl[k4 * 2 + 1] = __nv_bfloat162(lz, lw);
    }
    #pragma unroll
    for (int h = 0; h < 4; h++) {
        ss[h] = warp_reduce(ss[h]);
        sd[h] = warp_reduce(sd[h]);
    }
    if (lane == 0) {
        *(float4*)(g_ssrc + gw * 4) = make_float4(ss[0], ss[1], ss[2], ss[3]);
        *(float4*)(g_sdst + gw * 4) = make_float4(sd[0], sd[1], sd[2], sd[3]);
    }
}

// ---------------- 2b) split + transpose B ----------------
__global__ void split_b_kernel(const float* __restrict__ Wm) {
    size_t i = (size_t)blockIdx.x * blockDim.x + threadIdx.x;
    size_t tot = (size_t)PAD_N * IN_DIM;
    if (i >= tot) return;
    int n = (int)(i / IN_DIM);
    int k = (int)(i % IN_DIM);
    float v = (n < HID) ? Wm[(size_t)k * HID + n] : 0.0f;
    __nv_bfloat16 hi = __float2bfloat16(v);
    __nv_bfloat16 lo = __float2bfloat16(v - __bfloat162float(hi));
    g_Bh[i] = hi;
    g_Bl[i] = lo;
}

// ---------------- 3) init: denom=0, cnt=0 ----------------
__global__ void init_kernel() {
    int tid = blockIdx.x * blockDim.x + threadIdx.x;
    if (tid < N_NODES * HEADS) g_denom[tid] = 0.0f;
    if (tid < N_NODES) g_cnt[tid] = 0;
}

// ---------------- 4) HMMA GEMM (unchanged from R5) ----------------
__global__ void __launch_bounds__(256) gemm_mma_kernel() {
    extern __shared__ char smem[];
    const uint32_t sbase = smem_u32(smem);
    const int t = threadIdx.x;
    const int lane = t & 31;
    const int warp = t >> 5;
    const int wm = warp >> 1;
    const int wn = warp & 1;
    const int n0 = blockIdx.x * BN;
    const int row0 = blockIdx.y * BM;

    float acc[2][4][4];
    #pragma unroll
    for (int mi = 0; mi < 2; mi++)
        #pragma unroll
        for (int nj = 0; nj < 4; nj++)
            #pragma unroll
            for (int q = 0; q < 4; q++) acc[mi][nj][q] = 0.0f;

    auto load_chunk = [&](int c, int buf) {
        #pragma unroll
        for (int i = 0; i < 2; i++) {
            int lin = i * 256 + t;
            int r = lin >> 2, seg = lin & 3;
            int gr = row0 + r; if (gr > N_NODES - 1) gr = N_NODES - 1;
            size_t go = (size_t)gr * IN_DIM + c * BK + seg * 8;
            uint32_t so = (uint32_t)(r * A_STRIDE + seg * 16);
            cp_async16(sbase + SA_OFF(buf, 0) + so, g_Ah + go);
            cp_async16(sbase + SA_OFF(buf, 1) + so, g_Al + go);
        }
        {
            int r = t >> 2, seg = t & 3;
            size_t go = (size_t)(n0 + r) * IN_DIM + c * BK + seg * 8;
            uint32_t so = (uint32_t)(r * A_STRIDE + seg * 16);
            cp_async16(sbase + SB_OFF(buf, 0) + so, g_Bh + go);
            cp_async16(sbase + SB_OFF(buf, 1) + so, g_Bl + go);
        }
        cp_commit();
    };

    load_chunk(0, 0);
    load_chunk(1, 1);

    for (int c = 0; c < NCHUNK; c++) {
        if (c == NCHUNK - 1) cp_wait<0>(); else cp_wait<1>();
        __syncthreads();
        const int buf = c & 1;

        #pragma unroll
        for (int k16 = 0; k16 < BK; k16 += 16) {
            uint32_t af[2][2][4];
            #pragma unroll
            for (int ver = 0; ver < 2; ver++)
                #pragma unroll
                for (int mi = 0; mi < 2; mi++) {
                    int r = wm * 32 + mi * 16 + (lane & 7) + ((lane >> 3) & 1) * 8;
                    int colB = (k16 + (lane >> 4) * 8) * 2;
                    ldm_x4(af[ver][mi], sbase + SA_OFF(buf, ver) + r * A_STRIDE + colB);
                }
            uint32_t bf[2][4][2];
            #pragma unroll
            for (int ver = 0; ver < 2; ver++)
                #pragma unroll
                for (int pr = 0; pr < 2; pr++) {
                    uint32_t r4[4];
                    int n = wn * 32 + pr * 16 + ((lane >> 4) & 1) * 8 + (lane & 7);
                    int colB = (k16 + ((lane >> 3) & 1) * 8) * 2;
                    ldm_x4(r4, sbase + SB_OFF(buf, ver) + n * A_STRIDE + colB);
                    bf[ver][pr * 2 + 0][0] = r4[0]; bf[ver][pr * 2 + 0][1] = r4[1];
                    bf[ver][pr * 2 + 1][0] = r4[2]; bf[ver][pr * 2 + 1][1] = r4[3];
                }
            #pragma unroll
            for (int mi = 0; mi < 2; mi++)
                #pragma unroll
                for (int nj = 0; nj < 4; nj++) {
                    mma16816(acc[mi][nj], af[0][mi], bf[0][nj]);
                    mma16816(acc[mi][nj], af[0][mi], bf[1][nj]);
                    mma16816(acc[mi][nj], af[1][mi], bf[0][nj]);
                }
        }
        __syncthreads();
        if (c + 2 < NCHUNK) load_chunk(c + 2, buf);
    }

    #pragma unroll
    for (int mi = 0; mi < 2; mi++)
        #pragma unroll
        for (int nj = 0; nj < 4; nj++) {
            int tileN = n0 + wn * 32 + nj * 8;
            if (tileN >= HID) continue;
            int col = tileN + 2 * (lane & 3);
            int r0 = row0 + wm * 32 + mi * 16 + (lane >> 2);
            if (r0 < N_NODES)
                *(float2*)(g_h + (size_t)r0 * HID + col) =
                    make_float2(acc[mi][nj][0], acc[mi][nj][1]);
            int r1 = r0 + 8;
            if (r1 < N_NODES)
                *(float2*)(g_h + (size_t)r1 * HID + col) =
                    make_float2(acc[mi][nj][2], acc[mi][nj][3]);
        }
}

// ---------------- 5) rel logits ----------------
__global__ void rel_logits_kernel(const float* __restrict__ rel_feat,
                                  const float* __restrict__ a_rel) {
    int wid  = (blockIdx.x * blockDim.x + threadIdx.x) >> 5;
    int lane = threadIdx.x & 31;
    if (wid >= NUM_REL * HEADS) return;
    int r = wid >> 2, h = wid & 3;
    const float* rp = rel_feat + (size_t)r * HID + h * OUT_DIM;
    const float* ar = a_rel + h * OUT_DIM;
    float s = 0.f;
    for (int d = lane; d < OUT_DIM; d += 32) s = fmaf(rp[d], ar[d], s);
    s = warp_reduce(s);
    if (lane == 0) g_rlog[wid] = s;
}

// ---------------- 6) edge pass: logit -> leaky -> exp -> denom (+count) ----------
// softmax is shift-invariant; logits are O(10) so exp cannot overflow -> no max pass
__global__ void edge_lse_kernel(const void* __restrict__ ei,
                                const void* __restrict__ et) {
    int idx = blockIdx.x * blockDim.x + threadIdx.x;
    if (idx >= E_EDGES * HEADS) return;
    int e = idx >> 2, h = idx & 3;
    int s = load_idx(ei, e);
    int d = load_idx(ei, E_EDGES + e);
    int r = load_idx(et, e);
    float x = g_ssrc[s * 4 + h] + g_sdst[d * 4 + h] + g_rlog[r * 4 + h];
    x = (x >= 0.f) ? x : NEG_SLOPE * x;
    float ev = expf(x);
    g_elog[idx] = ev;
    atomicAdd(&g_denom[d * 4 + h], ev);
    if (h == 0) atomicAdd(&g_cnt[d], 1);
}

// ---------------- 7) exclusive scan of counts (single CTA) ----------------
__global__ void scan_kernel() {
    __shared__ int warp_sums[32];
    __shared__ int s_base;
    const int t = threadIdx.x;          // 1024 threads
    const int lane = t & 31, wid = t >> 5;
    if (t == 0) s_base = 0;
    __syncthreads();
    const int nchunks = (N_NODES + 1023) / 1024;
    for (int ch = 0; ch < nchunks; ch++) {
        int i = ch * 1024 + t;
        int v = (i < N_NODES) ? g_cnt[i] : 0;
        int x = v;
        #pragma unroll
        for (int o = 1; o < 32; o <<= 1) {
            int y = __shfl_up_sync(0xffffffffu, x, o);
            if (lane >= o) x += y;
        }
        if (lane == 31) warp_sums[wid] = x;
        __syncthreads();
        if (wid == 0) {
            int w = warp_sums[lane];
            #pragma unroll
            for (int o = 1; o < 32; o <<= 1) {
                int y = __shfl_up_sync(0xffffffffu, w, o);
                if (lane >= o) w += y;
            }
            warp_sums[lane] = w;        // inclusive warp-sum scan
        }
        __syncthreads();
        int warp_off = (wid == 0) ? 0 : warp_sums[wid - 1];
        int excl = s_base + warp_off + (x - v);
        if (i < N_NODES) { g_rowptr[i] = excl; g_cursor[i] = excl; }
        __syncthreads();
        if (t == 0) s_base += warp_sums[31];
        __syncthreads();
    }
    if (t == 0) g_rowptr[N_NODES] = s_base;
}

// ---------------- 8) CSR fill ----------------
__global__ void fill_kernel(const void* __restrict__ ei) {
    int e = blockIdx.x * blockDim.x + threadIdx.x;
    if (e >= E_EDGES) return;
    int d = load_idx(ei, E_EDGES + e);
    int pos = atomicAdd(&g_cursor[d], 1);
    g_csre[pos] = e;
}

// ---------------- 9) aggregate: warp per node, no atomics ----------------
__global__ void __launch_bounds__(256) agg_kernel(const void* __restrict__ ei) {
    int n    = (blockIdx.x * blockDim.x + threadIdx.x) >> 5;
    int lane = threadIdx.x & 31;
    if (n >= N_NODES) return;
    int rp0 = g_rowptr[n], rp1 = g_rowptr[n + 1];
    float4 dn = *(const float4*)(g_denom + n * 4);
    float r0 = (rp1 > rp0) ? 1.0f / dn.x : 0.0f;
    float r1 = (rp1 > rp0) ? 1.0f / dn.y : 0.0f;
    float r2 = (rp1 > rp0) ? 1.0f / dn.z : 0.0f;
    float r3 = (rp1 > rp0) ? 1.0f / dn.w : 0.0f;
    float4 acc[7];
    #pragma unroll
    for (int it = 0; it < 7; it++) acc[it] = make_float4(0.f, 0.f, 0.f, 0.f);

    for (int j = rp0; j < rp1; j++) {
        int e = g_csre[j];
        int s = load_idx(ei, e);
        float4 ev = *(const float4*)(g_elog + e * 4);
        float a0 = ev.x * r0, a1 = ev.y * r1, a2 = ev.z * r2, a3 = ev.w * r3;
        const float4* hs = (const float4*)(g_h + (size_t)s * HID);
        #pragma unroll
        for (int it = 0; it < 7; it++) {
            int c = lane + it * 32;
            if (c < HID / 4) {
                float a = (c < 50) ? a0 : (c < 100) ? a1 : (c < 150) ? a2 : a3;
                float4 v = hs[c];
                acc[it].x = fmaf(a, v.x, acc[it].x);
                acc[it].y = fmaf(a, v.y, acc[it].y);
                acc[it].z = fmaf(a, v.z, acc[it].z);
                acc[it].w = fmaf(a, v.w, acc[it].w);
            }
        }
    }
    float4* op = (float4*)(g_out + (size_t)n * HID);
    #pragma unroll
    for (int it = 0; it < 7; it++) {
        int c = lane + it * 32;
        if (c < HID / 4) op[c] = acc[it];
    }
}

// ---------------- 10) DistMult ----------------
__global__ void distmult_kernel(const float* __restrict__ bias,
                                const float* __restrict__ rel_emb,
                                const void* __restrict__ si,
                                const void* __restrict__ ri,
                                const void* __restrict__ di,
                                float* __restrict__ out) {
    int wid  = (blockIdx.x * blockDim.x + threadIdx.x) >> 5;
    int lane = threadIdx.x & 31;
    if (wid >= BATCH) return;
    int s = load_idx(si, wid);
    int r = load_idx(ri, wid);
    int d = load_idx(di, wid);
    const float* ps = g_out + (size_t)s * HID;
    const float* pd = g_out + (size_t)d * HID;
    const float* pr = rel_emb + (size_t)r * HID;
    float acc = 0.f;
    for (int k = lane; k < HID; k += 32) {
        float b = bias[k];
        acc = fmaf((ps[k] + b) * pr[k], (pd[k] + b), acc);
    }
    acc = warp_reduce(acc);
    if (lane == 0) out[wid] = acc;
}

// ---------------- launch ----------------
extern "C" void kernel_launch(void* const* d_in, const int* in_sizes, int n_in,
                              void* d_out, int out_size) {
    const float* node_emb   = (const float*)d_in[0];
    const float* Wm         = (const float*)d_in[1];
    const float* bias       = (const float*)d_in[2];
    const float* a_src      = (const float*)d_in[3];
    const float* a_dst      = (const float*)d_in[4];
    const float* a_rel      = (const float*)d_in[5];
    const float* rel_feat   = (const float*)d_in[6];
    const float* rel_emb    = (const float*)d_in[7];
    const void*  edge_index = d_in[8];
    const void*  edge_type  = d_in[9];
    const void*  src_ids    = d_in[10];
    const void*  rel_ids    = d_in[11];
    const void*  dst_ids    = d_in[12];
    float* out = (float*)d_out;

    cudaFuncSetAttribute(gemm_mma_kernel,
                         cudaFuncAttributeMaxDynamicSharedMemorySize, SM_TOT);

    detect_dtype_kernel<<<1, 32>>>(edge_index);
    cvec_kernel<<<(IN_DIM * HEADS * 32 + 255) / 256, 256>>>(Wm, a_src, a_dst);
    rel_logits_kernel<<<(NUM_REL * HEADS * 32 + 255) / 256, 256>>>(rel_feat, a_rel);

    split_a_kernel<<<(N_NODES * 32 + 255) / 256, 256>>>(node_emb);
    {
        size_t totb = (size_t)PAD_N * IN_DIM;
        split_b_kernel<<<(unsigned)((totb + 255) / 256), 256>>>(Wm);
    }
    init_kernel<<<(N_NODES * HEADS + 255) / 256, 256>>>();

    dim3 ggrid(NT_N, NT_M);
    gemm_mma_kernel<<<ggrid, 256, SM_TOT>>>();

    edge_lse_kernel<<<(E_EDGES * HEADS + 255) / 256, 256>>>(edge_index, edge_type);
    scan_kernel<<<1, 1024>>>();
    fill_kernel<<<(E_EDGES + 255) / 256, 256>>>(edge_index);
    agg_kernel<<<(N_NODES * 32 + 255) / 256, 256>>>(edge_index);

    distmult_kernel<<<(BATCH * 32 + 255) / 256, 256>>>(bias, rel_emb,
                                                       src_ids, rel_ids, dst_ids, out);
}

// round 7
// speedup vs baseline: 1.0807x; 1.0807x over previous
#include <cuda_runtime.h>
#include <cuda_bf16.h>
#include <cfloat>
#include <cstdint>

#define N_NODES 50000
#define IN_DIM  1024
#define E_EDGES 100000
#define NUM_REL 40
#define HEADS   4
#define OUT_DIM 200
#define HID     800
#define BATCH   8192
#define NEG_SLOPE 0.2f

#define BM 128
#define BN 64
#define BK 32
#define NCHUNK (IN_DIM / BK)            // 32
#define NT_M ((N_NODES + BM - 1) / BM)  // 391
#define NT_N 13                         // ceil(800/64)
#define PAD_N (NT_N * BN)               // 832

// smem layout (bytes from dynamic base); padded row stride 80B (40 bf16)
#define A_STRIDE 80
#define A_VER_SZ (128 * A_STRIDE)       // 10240
#define B_VER_SZ (64 * A_STRIDE)        // 5120
#define SA_OFF(buf, ver) ((buf) * (2 * A_VER_SZ) + (ver) * A_VER_SZ)
#define SB_OFF(buf, ver) (4 * A_VER_SZ + (buf) * (2 * B_VER_SZ) + (ver) * B_VER_SZ)
#define SM_TOT (4 * A_VER_SZ + 4 * B_VER_SZ)   // 61440

// ---------------- scratch (device globals) ----------------
__device__ __align__(16) float g_h  [(size_t)N_NODES * HID];
__device__ __align__(16) float g_out[(size_t)N_NODES * HID];
__device__ __align__(16) __nv_bfloat16 g_Ah[(size_t)N_NODES * IN_DIM];
__device__ __align__(16) __nv_bfloat16 g_Al[(size_t)N_NODES * IN_DIM];
__device__ __align__(16) __nv_bfloat16 g_Bh[(size_t)PAD_N * IN_DIM];  // B^T, K-major
__device__ __align__(16) __nv_bfloat16 g_Bl[(size_t)PAD_N * IN_DIM];
__device__ __align__(16) float g_csrc[IN_DIM * HEADS];   // (W @ a_src per head) [k][h]
__device__ __align__(16) float g_cdst[IN_DIM * HEADS];
__device__ __align__(16) float g_ssrc  [N_NODES * HEADS];
__device__ __align__(16) float g_sdst  [N_NODES * HEADS];
__device__ float g_rlog  [NUM_REL * HEADS];
__device__ __align__(16) float g_denom [N_NODES * HEADS];
__device__ __align__(16) float g_elog  [E_EDGES * HEADS];
__device__ int   g_cnt   [N_NODES];
__device__ int   g_rowptr[N_NODES + 1];
__device__ int   g_cursor[N_NODES];
__device__ int   g_csre  [E_EDGES];
__device__ int   g_is64;

// ---------------- helpers ----------------
__device__ __forceinline__ int load_idx(const void* p, int i) {
    if (g_is64) return (int)((const long long*)p)[i];
    return ((const int*)p)[i];
}
__device__ __forceinline__ float warp_reduce(float v) {
    #pragma unroll
    for (int o = 16; o > 0; o >>= 1) v += __shfl_down_sync(0xffffffffu, v, o);
    return v;
}
__device__ __forceinline__ uint32_t smem_u32(const void* p) {
    uint32_t a;
    asm("{ .reg .u64 t; cvta.to.shared.u64 t, %1; cvt.u32.u64 %0, t; }" : "=r"(a) : "l"(p));
    return a;
}
__device__ __forceinline__ void cp_async16(uint32_t s, const void* g) {
    asm volatile("cp.async.cg.shared.global [%0], [%1], 16;" :: "r"(s), "l"(g));
}
__device__ __forceinline__ void cp_commit() {
    asm volatile("cp.async.commit_group;" ::: "memory");
}
template<int NN> __device__ __forceinline__ void cp_wait() {
    asm volatile("cp.async.wait_group %0;" :: "n"(NN) : "memory");
}
__device__ __forceinline__ void ldm_x4(uint32_t* r, uint32_t addr) {
    asm volatile("ldmatrix.sync.aligned.m8n8.x4.shared.b16 {%0,%1,%2,%3}, [%4];"
                 : "=r"(r[0]), "=r"(r[1]), "=r"(r[2]), "=r"(r[3]) : "r"(addr));
}
__device__ __forceinline__ void mma16816(float* d, const uint32_t* a, const uint32_t* b) {
    asm volatile(
        "mma.sync.aligned.m16n8k16.row.col.f32.bf16.bf16.f32 "
        "{%0,%1,%2,%3}, {%4,%5,%6,%7}, {%8,%9}, {%0,%1,%2,%3};"
        : "+f"(d[0]), "+f"(d[1]), "+f"(d[2]), "+f"(d[3])
        : "r"(a[0]), "r"(a[1]), "r"(a[2]), "r"(a[3]), "r"(b[0]), "r"(b[1]));
}

// ---------------- 0) dtype detection ----------------
__global__ void detect_dtype_kernel(const void* edge_index) {
    if (threadIdx.x == 0 && blockIdx.x == 0) {
        const long long* p = (const long long*)edge_index;
        int ok = 1;
        for (int i = 0; i < 64; i++) {
            long long v = p[i];
            if (v < 0 || v >= N_NODES) { ok = 0; break; }
        }
        g_is64 = ok;
    }
}

// ---------------- 1) c vectors: c_src[k][h] = sum_d W[k, h*200+d] * a_src[h][d] -----
__global__ void cvec_kernel(const float* __restrict__ Wm,
                            const float* __restrict__ a_src,
                            const float* __restrict__ a_dst) {
    int wid  = (blockIdx.x * blockDim.x + threadIdx.x) >> 5;
    int lane = threadIdx.x & 31;
    if (wid >= IN_DIM * HEADS) return;
    int k = wid >> 2, h = wid & 3;
    const float* wrow = Wm + (size_t)k * HID + h * OUT_DIM;
    const float* as = a_src + h * OUT_DIM;
    const float* ad = a_dst + h * OUT_DIM;
    float cs = 0.f, cd = 0.f;
    for (int d = lane; d < OUT_DIM; d += 32) {
        float w = wrow[d];
        cs = fmaf(w, as[d], cs);
        cd = fmaf(w, ad[d], cd);
    }
    cs = warp_reduce(cs);
    cd = warp_reduce(cd);
    if (lane == 0) { g_csrc[k * 4 + h] = cs; g_cdst[k * 4 + h] = cd; }
}

// ---------------- 2) init: ssrc/sdst/denom = 0, cnt = 0 ----------------
__global__ void init_kernel() {
    int tid = blockIdx.x * blockDim.x + threadIdx.x;
    if (tid < N_NODES * HEADS) {
        g_denom[tid] = 0.0f;
        g_ssrc[tid]  = 0.0f;
        g_sdst[tid]  = 0.0f;
    }
    if (tid < N_NODES) g_cnt[tid] = 0;
}

// ---------------- 3a) split A into bf16 hi/lo + fused s_src/s_dst ----------------
// thread t owns k = 4t..4t+3 for ALL nodes (c stays in registers).
// grid-stride over nodes; warp butterfly-reduces its 128-k slice, lane0 atomicAdds.
__global__ void __launch_bounds__(256) split_a_kernel(const float* __restrict__ A) {
    const int t = threadIdx.x;
    const int lane = t & 31;
    float4 cs[4], cd[4];
    #pragma unroll
    for (int q = 0; q < 4; q++) {
        cs[q] = ((const float4*)g_csrc)[t * 4 + q];
        cd[q] = ((const float4*)g_cdst)[t * 4 + q];
    }
    for (int n = blockIdx.x; n < N_NODES; n += gridDim.x) {
        float4 a = ((const float4*)(A + (size_t)n * IN_DIM))[t];
        float av[4] = {a.x, a.y, a.z, a.w};
        float ss0 = 0.f, ss1 = 0.f, ss2 = 0.f, ss3 = 0.f;
        float sd0 = 0.f, sd1 = 0.f, sd2 = 0.f, sd3 = 0.f;
        #pragma unroll
        for (int q = 0; q < 4; q++) {
            ss0 = fmaf(av[q], cs[q].x, ss0); ss1 = fmaf(av[q], cs[q].y, ss1);
            ss2 = fmaf(av[q], cs[q].z, ss2); ss3 = fmaf(av[q], cs[q].w, ss3);
            sd0 = fmaf(av[q], cd[q].x, sd0); sd1 = fmaf(av[q], cd[q].y, sd1);
            sd2 = fmaf(av[q], cd[q].z, sd2); sd3 = fmaf(av[q], cd[q].w, sd3);
        }
        // bf16 split store (coalesced: 8B per thread)
        __nv_bfloat16 hx = __float2bfloat16(a.x), hy = __float2bfloat16(a.y);
        __nv_bfloat16 hz = __float2bfloat16(a.z), hw = __float2bfloat16(a.w);
        __nv_bfloat16 lx = __float2bfloat16(a.x - __bfloat162float(hx));
        __nv_bfloat16 ly = __float2bfloat16(a.y - __bfloat162float(hy));
        __nv_bfloat16 lz = __float2bfloat16(a.z - __bfloat162float(hz));
        __nv_bfloat16 lw = __float2bfloat16(a.w - __bfloat162float(hw));
        __nv_bfloat162* ph = (__nv_bfloat162*)(g_Ah + (size_t)n * IN_DIM) + t * 2;
        __nv_bfloat162* pl = (__nv_bfloat162*)(g_Al + (size_t)n * IN_DIM) + t * 2;
        ph[0] = __nv_bfloat162(hx, hy); ph[1] = __nv_bfloat162(hz, hw);
        pl[0] = __nv_bfloat162(lx, ly); pl[1] = __nv_bfloat162(lz, lw);
        // butterfly reduce 8 values across warp
        #pragma unroll
        for (int o = 16; o > 0; o >>= 1) {
            ss0 += __shfl_xor_sync(0xffffffffu, ss0, o);
            ss1 += __shfl_xor_sync(0xffffffffu, ss1, o);
            ss2 += __shfl_xor_sync(0xffffffffu, ss2, o);
            ss3 += __shfl_xor_sync(0xffffffffu, ss3, o);
            sd0 += __shfl_xor_sync(0xffffffffu, sd0, o);
            sd1 += __shfl_xor_sync(0xffffffffu, sd1, o);
            sd2 += __shfl_xor_sync(0xffffffffu, sd2, o);
            sd3 += __shfl_xor_sync(0xffffffffu, sd3, o);
        }
        if (lane == 0) {
            atomicAdd(&g_ssrc[n * 4 + 0], ss0);
            atomicAdd(&g_ssrc[n * 4 + 1], ss1);
            atomicAdd(&g_ssrc[n * 4 + 2], ss2);
            atomicAdd(&g_ssrc[n * 4 + 3], ss3);
            atomicAdd(&g_sdst[n * 4 + 0], sd0);
            atomicAdd(&g_sdst[n * 4 + 1], sd1);
            atomicAdd(&g_sdst[n * 4 + 2], sd2);
            atomicAdd(&g_sdst[n * 4 + 3], sd3);
        }
    }
}

// ---------------- 3b) split + transpose B via smem tile ----------------
// W[k, n] -> Bt[n, k] hi/lo.  block 32x8, tile 32x32, grid (IN_DIM/32, PAD_N/32)
__global__ void __launch_bounds__(256) split_b_kernel(const float* __restrict__ Wm) {
    __shared__ float tile[32][33];
    const int tx = threadIdx.x;        // 0..31
    const int ty = threadIdx.y;        // 0..7
    const int k0 = blockIdx.x * 32;
    const int n0 = blockIdx.y * 32;
    #pragma unroll
    for (int j = 0; j < 4; j++) {
        int k = k0 + ty + j * 8;
        int n = n0 + tx;
        tile[ty + j * 8][tx] = (n < HID) ? Wm[(size_t)k * HID + n] : 0.0f;
    }
    __syncthreads();
    #pragma unroll
    for (int j = 0; j < 4; j++) {
        int n = n0 + ty + j * 8;
        int k = k0 + tx;
        float v = tile[tx][ty + j * 8];
        __nv_bfloat16 hi = __float2bfloat16(v);
        __nv_bfloat16 lo = __float2bfloat16(v - __bfloat162float(hi));
        g_Bh[(size_t)n * IN_DIM + k] = hi;
        g_Bl[(size_t)n * IN_DIM + k] = lo;
    }
}

// ---------------- 4) HMMA GEMM (unchanged) ----------------
__global__ void __launch_bounds__(256) gemm_mma_kernel() {
    extern __shared__ char smem[];
    const uint32_t sbase = smem_u32(smem);
    const int t = threadIdx.x;
    const int lane = t & 31;
    const int warp = t >> 5;
    const int wm = warp >> 1;
    const int wn = warp & 1;
    const int n0 = blockIdx.x * BN;
    const int row0 = blockIdx.y * BM;

    float acc[2][4][4];
    #pragma unroll
    for (int mi = 0; mi < 2; mi++)
        #pragma unroll
        for (int nj = 0; nj < 4; nj++)
            #pragma unroll
            for (int q = 0; q < 4; q++) acc[mi][nj][q] = 0.0f;

    auto load_chunk = [&](int c, int buf) {
        #pragma unroll
        for (int i = 0; i < 2; i++) {
            int lin = i * 256 + t;
            int r = lin >> 2, seg = lin & 3;
            int gr = row0 + r; if (gr > N_NODES - 1) gr = N_NODES - 1;
            size_t go = (size_t)gr * IN_DIM + c * BK + seg * 8;
            uint32_t so = (uint32_t)(r * A_STRIDE + seg * 16);
            cp_async16(sbase + SA_OFF(buf, 0) + so, g_Ah + go);
            cp_async16(sbase + SA_OFF(buf, 1) + so, g_Al + go);
        }
        {
            int r = t >> 2, seg = t & 3;
            size_t go = (size_t)(n0 + r) * IN_DIM + c * BK + seg * 8;
            uint32_t so = (uint32_t)(r * A_STRIDE + seg * 16);
            cp_async16(sbase + SB_OFF(buf, 0) + so, g_Bh + go);
            cp_async16(sbase + SB_OFF(buf, 1) + so, g_Bl + go);
        }
        cp_commit();
    };

    load_chunk(0, 0);
    load_chunk(1, 1);

    for (int c = 0; c < NCHUNK; c++) {
        if (c == NCHUNK - 1) cp_wait<0>(); else cp_wait<1>();
        __syncthreads();
        const int buf = c & 1;

        #pragma unroll
        for (int k16 = 0; k16 < BK; k16 += 16) {
            uint32_t af[2][2][4];
            #pragma unroll
            for (int ver = 0; ver < 2; ver++)
                #pragma unroll
                for (int mi = 0; mi < 2; mi++) {
                    int r = wm * 32 + mi * 16 + (lane & 7) + ((lane >> 3) & 1) * 8;
                    int colB = (k16 + (lane >> 4) * 8) * 2;
                    ldm_x4(af[ver][mi], sbase + SA_OFF(buf, ver) + r * A_STRIDE + colB);
                }
            uint32_t bf[2][4][2];
            #pragma unroll
            for (int ver = 0; ver < 2; ver++)
                #pragma unroll
                for (int pr = 0; pr < 2; pr++) {
                    uint32_t r4[4];
                    int n = wn * 32 + pr * 16 + ((lane >> 4) & 1) * 8 + (lane & 7);
                    int colB = (k16 + ((lane >> 3) & 1) * 8) * 2;
                    ldm_x4(r4, sbase + SB_OFF(buf, ver) + n * A_STRIDE + colB);
                    bf[ver][pr * 2 + 0][0] = r4[0]; bf[ver][pr * 2 + 0][1] = r4[1];
                    bf[ver][pr * 2 + 1][0] = r4[2]; bf[ver][pr * 2 + 1][1] = r4[3];
                }
            #pragma unroll
            for (int mi = 0; mi < 2; mi++)
                #pragma unroll
                for (int nj = 0; nj < 4; nj++) {
                    mma16816(acc[mi][nj], af[0][mi], bf[0][nj]);
                    mma16816(acc[mi][nj], af[0][mi], bf[1][nj]);
                    mma16816(acc[mi][nj], af[1][mi], bf[0][nj]);
                }
        }
        __syncthreads();
        if (c + 2 < NCHUNK) load_chunk(c + 2, buf);
    }

    #pragma unroll
    for (int mi = 0; mi < 2; mi++)
        #pragma unroll
        for (int nj = 0; nj < 4; nj++) {
            int tileN = n0 + wn * 32 + nj * 8;
            if (tileN >= HID) continue;
            int col = tileN + 2 * (lane & 3);
            int r0 = row0 + wm * 32 + mi * 16 + (lane >> 2);
            if (r0 < N_NODES)
                *(float2*)(g_h + (size_t)r0 * HID + col) =
                    make_float2(acc[mi][nj][0], acc[mi][nj][1]);
            int r1 = r0 + 8;
            if (r1 < N_NODES)
                *(float2*)(g_h + (size_t)r1 * HID + col) =
                    make_float2(acc[mi][nj][2], acc[mi][nj][3]);
        }
}

// ---------------- 5) rel logits ----------------
__global__ void rel_logits_kernel(const float* __restrict__ rel_feat,
                                  const float* __restrict__ a_rel) {
    int wid  = (blockIdx.x * blockDim.x + threadIdx.x) >> 5;
    int lane = threadIdx.x & 31;
    if (wid >= NUM_REL * HEADS) return;
    int r = wid >> 2, h = wid & 3;
    const float* rp = rel_feat + (size_t)r * HID + h * OUT_DIM;
    const float* ar = a_rel + h * OUT_DIM;
    float s = 0.f;
    for (int d = lane; d < OUT_DIM; d += 32) s = fmaf(rp[d], ar[d], s);
    s = warp_reduce(s);
    if (lane == 0) g_rlog[wid] = s;
}

// ---------------- 6) edge pass: logit -> leaky -> exp -> denom (+count) ----------
__global__ void edge_lse_kernel(const void* __restrict__ ei,
                                const void* __restrict__ et) {
    int idx = blockIdx.x * blockDim.x + threadIdx.x;
    if (idx >= E_EDGES * HEADS) return;
    int e = idx >> 2, h = idx & 3;
    int s = load_idx(ei, e);
    int d = load_idx(ei, E_EDGES + e);
    int r = load_idx(et, e);
    float x = g_ssrc[s * 4 + h] + g_sdst[d * 4 + h] + g_rlog[r * 4 + h];
    x = (x >= 0.f) ? x : NEG_SLOPE * x;
    float ev = expf(x);
    g_elog[idx] = ev;
    atomicAdd(&g_denom[d * 4 + h], ev);
    if (h == 0) atomicAdd(&g_cnt[d], 1);
}

// ---------------- 7) exclusive scan of counts (single CTA) ----------------
__global__ void scan_kernel() {
    __shared__ int warp_sums[32];
    __shared__ int s_base;
    const int t = threadIdx.x;
    const int lane = t & 31, wid = t >> 5;
    if (t == 0) s_base = 0;
    __syncthreads();
    const int nchunks = (N_NODES + 1023) / 1024;
    for (int ch = 0; ch < nchunks; ch++) {
        int i = ch * 1024 + t;
        int v = (i < N_NODES) ? g_cnt[i] : 0;
        int x = v;
        #pragma unroll
        for (int o = 1; o < 32; o <<= 1) {
            int y = __shfl_up_sync(0xffffffffu, x, o);
            if (lane >= o) x += y;
        }
        if (lane == 31) warp_sums[wid] = x;
        __syncthreads();
        if (wid == 0) {
            int w = warp_sums[lane];
            #pragma unroll
            for (int o = 1; o < 32; o <<= 1) {
                int y = __shfl_up_sync(0xffffffffu, w, o);
                if (lane >= o) w += y;
            }
            warp_sums[lane] = w;
        }
        __syncthreads();
        int warp_off = (wid == 0) ? 0 : warp_sums[wid - 1];
        int excl = s_base + warp_off + (x - v);
        if (i < N_NODES) { g_rowptr[i] = excl; g_cursor[i] = excl; }
        __syncthreads();
        if (t == 0) s_base += warp_sums[31];
        __syncthreads();
    }
    if (t == 0) g_rowptr[N_NODES] = s_base;
}

// ---------------- 8) CSR fill ----------------
__global__ void fill_kernel(const void* __restrict__ ei) {
    int e = blockIdx.x * blockDim.x + threadIdx.x;
    if (e >= E_EDGES) return;
    int d = load_idx(ei, E_EDGES + e);
    int pos = atomicAdd(&g_cursor[d], 1);
    g_csre[pos] = e;
}

// ---------------- 9) aggregate: warp per node, no atomics ----------------
__global__ void __launch_bounds__(256) agg_kernel(const void* __restrict__ ei) {
    int n    = (blockIdx.x * blockDim.x + threadIdx.x) >> 5;
    int lane = threadIdx.x & 31;
    if (n >= N_NODES) return;
    int rp0 = g_rowptr[n], rp1 = g_rowptr[n + 1];
    float4 dn = *(const float4*)(g_denom + n * 4);
    float r0 = (rp1 > rp0) ? 1.0f / dn.x : 0.0f;
    float r1 = (rp1 > rp0) ? 1.0f / dn.y : 0.0f;
    float r2 = (rp1 > rp0) ? 1.0f / dn.z : 0.0f;
    float r3 = (rp1 > rp0) ? 1.0f / dn.w : 0.0f;
    float4 acc[7];
    #pragma unroll
    for (int it = 0; it < 7; it++) acc[it] = make_float4(0.f, 0.f, 0.f, 0.f);

    for (int j = rp0; j < rp1; j++) {
        int e = g_csre[j];
        int s = load_idx(ei, e);
        float4 ev = *(const float4*)(g_elog + e * 4);
        float a0 = ev.x * r0, a1 = ev.y * r1, a2 = ev.z * r2, a3 = ev.w * r3;
        const float4* hs = (const float4*)(g_h + (size_t)s * HID);
        #pragma unroll
        for (int it = 0; it < 7; it++) {
            int c = lane + it * 32;
            if (c < HID / 4) {
                float a = (c < 50) ? a0 : (c < 100) ? a1 : (c < 150) ? a2 : a3;
                float4 v = hs[c];
                acc[it].x = fmaf(a, v.x, acc[it].x);
                acc[it].y = fmaf(a, v.y, acc[it].y);
                acc[it].z = fmaf(a, v.z, acc[it].z);
                acc[it].w = fmaf(a, v.w, acc[it].w);
            }
        }
    }
    float4* op = (float4*)(g_out + (size_t)n * HID);
    #pragma unroll
    for (int it = 0; it < 7; it++) {
        int c = lane + it * 32;
        if (c < HID / 4) op[c] = acc[it];
    }
}

// ---------------- 10) DistMult ----------------
__global__ void distmult_kernel(const float* __restrict__ bias,
                                const float* __restrict__ rel_emb,
                                const void* __restrict__ si,
                                const void* __restrict__ ri,
                                const void* __restrict__ di,
                                float* __restrict__ out) {
    int wid  = (blockIdx.x * blockDim.x + threadIdx.x) >> 5;
    int lane = threadIdx.x & 31;
    if (wid >= BATCH) return;
    int s = load_idx(si, wid);
    int r = load_idx(ri, wid);
    int d = load_idx(di, wid);
    const float* ps = g_out + (size_t)s * HID;
    const float* pd = g_out + (size_t)d * HID;
    const float* pr = rel_emb + (size_t)r * HID;
    float acc = 0.f;
    for (int k = lane; k < HID; k += 32) {
        float b = bias[k];
        acc = fmaf((ps[k] + b) * pr[k], (pd[k] + b), acc);
    }
    acc = warp_reduce(acc);
    if (lane == 0) out[wid] = acc;
}

// ---------------- launch ----------------
extern "C" void kernel_launch(void* const* d_in, const int* in_sizes, int n_in,
                              void* d_out, int out_size) {
    const float* node_emb   = (const float*)d_in[0];
    const float* Wm         = (const float*)d_in[1];
    const float* bias       = (const float*)d_in[2];
    const float* a_src      = (const float*)d_in[3];
    const float* a_dst      = (const float*)d_in[4];
    const float* a_rel      = (const float*)d_in[5];
    const float* rel_feat   = (const float*)d_in[6];
    const float* rel_emb    = (const float*)d_in[7];
    const void*  edge_index = d_in[8];
    const void*  edge_type  = d_in[9];
    const void*  src_ids    = d_in[10];
    const void*  rel_ids    = d_in[11];
    const void*  dst_ids    = d_in[12];
    float* out = (float*)d_out;

    cudaFuncSetAttribute(gemm_mma_kernel,
                         cudaFuncAttributeMaxDynamicSharedMemorySize, SM_TOT);

    detect_dtype_kernel<<<1, 32>>>(edge_index);
    cvec_kernel<<<(IN_DIM * HEADS * 32 + 255) / 256, 256>>>(Wm, a_src, a_dst);
    rel_logits_kernel<<<(NUM_REL * HEADS * 32 + 255) / 256, 256>>>(rel_feat, a_rel);
    init_kernel<<<(N_NODES * HEADS + 255) / 256, 256>>>();

    split_a_kernel<<<592, 256>>>(node_emb);
    {
        dim3 bgrid(IN_DIM / 32, PAD_N / 32);
        split_b_kernel<<<bgrid, dim3(32, 8)>>>(Wm);
    }

    dim3 ggrid(NT_N, NT_M);
    gemm_mma_kernel<<<ggrid, 256, SM_TOT>>>();

    edge_lse_kernel<<<(E_EDGES * HEADS + 255) / 256, 256>>>(edge_index, edge_type);
    scan_kernel<<<1, 1024>>>();
    fill_kernel<<<(E_EDGES + 255) / 256, 256>>>(edge_index);
    agg_kernel<<<(N_NODES * 32 + 255) / 256, 256>>>(edge_index);

    distmult_kernel<<<(BATCH * 32 + 255) / 256, 256>>>(bias, rel_emb,
                                                       src_ids, rel_ids, dst_ids, out);
}

// round 8
// speedup vs baseline: 1.5103x; 1.3975x over previous
#include <cuda_runtime.h>
#include <cuda_fp16.h>
#include <cfloat>
#include <cstdint>

#define N_NODES 50000
#define IN_DIM  1024
#define E_EDGES 100000
#define NUM_REL 40
#define HEADS   4
#define OUT_DIM 200
#define HID     800
#define BATCH   8192
#define NEG_SLOPE 0.2f

#define BM 128
#define BN 64
#define BK 32
#define NCHUNK (IN_DIM / BK)            // 32
#define NT_M ((N_NODES + BM - 1) / BM)  // 391
#define NT_N 13                         // ceil(800/64)
#define PAD_N (NT_N * BN)               // 832

// smem layout (bytes from dynamic base); padded row stride 80B (40 fp16)
#define A_STRIDE 80
#define A_VER_SZ (128 * A_STRIDE)       // 10240
#define B_VER_SZ (64 * A_STRIDE)        // 5120
#define SA_OFF(buf, ver) ((buf) * (2 * A_VER_SZ) + (ver) * A_VER_SZ)
#define SB_OFF(buf)      (4 * A_VER_SZ + (buf) * B_VER_SZ)
#define SM_TOT (4 * A_VER_SZ + 2 * B_VER_SZ)   // 51200

// ---------------- scratch (device globals) ----------------
__device__ __align__(16) float g_h  [(size_t)N_NODES * HID];
__device__ __align__(16) float g_out[(size_t)N_NODES * HID];
__device__ __align__(16) __half g_Ah[(size_t)N_NODES * IN_DIM];
__device__ __align__(16) __half g_Al[(size_t)N_NODES * IN_DIM];
__device__ __align__(16) __half g_Bh[(size_t)PAD_N * IN_DIM];   // W^T, K-major, fp16
__device__ __align__(16) float g_csrc[IN_DIM * HEADS];   // (W @ a_src per head) [k][h]
__device__ __align__(16) float g_cdst[IN_DIM * HEADS];
__device__ __align__(16) float g_ssrc  [N_NODES * HEADS];
__device__ __align__(16) float g_sdst  [N_NODES * HEADS];
__device__ float g_rlog  [NUM_REL * HEADS];
__device__ __align__(16) float g_denom [N_NODES * HEADS];
__device__ __align__(16) float g_elog  [E_EDGES * HEADS];
__device__ int   g_cnt   [N_NODES];
__device__ int   g_rowptr[N_NODES + 1];
__device__ int   g_cursor[N_NODES];
__device__ int   g_csre  [E_EDGES];
__device__ int   g_is64;

// ---------------- helpers ----------------
__device__ __forceinline__ int load_idx(const void* p, int i) {
    if (g_is64) return (int)((const long long*)p)[i];
    return ((const int*)p)[i];
}
__device__ __forceinline__ float warp_reduce(float v) {
    #pragma unroll
    for (int o = 16; o > 0; o >>= 1) v += __shfl_down_sync(0xffffffffu, v, o);
    return v;
}
__device__ __forceinline__ uint32_t smem_u32(const void* p) {
    uint32_t a;
    asm("{ .reg .u64 t; cvta.to.shared.u64 t, %1; cvt.u32.u64 %0, t; }" : "=r"(a) : "l"(p));
    return a;
}
__device__ __forceinline__ void cp_async16(uint32_t s, const void* g) {
    asm volatile("cp.async.cg.shared.global [%0], [%1], 16;" :: "r"(s), "l"(g));
}
__device__ __forceinline__ void cp_commit() {
    asm volatile("cp.async.commit_group;" ::: "memory");
}
template<int NN> __device__ __forceinline__ void cp_wait() {
    asm volatile("cp.async.wait_group %0;" :: "n"(NN) : "memory");
}
__device__ __forceinline__ void ldm_x4(uint32_t* r, uint32_t addr) {
    asm volatile("ldmatrix.sync.aligned.m8n8.x4.shared.b16 {%0,%1,%2,%3}, [%4];"
                 : "=r"(r[0]), "=r"(r[1]), "=r"(r[2]), "=r"(r[3]) : "r"(addr));
}
__device__ __forceinline__ void mma16816(float* d, const uint32_t* a, const uint32_t* b) {
    asm volatile(
        "mma.sync.aligned.m16n8k16.row.col.f32.f16.f16.f32 "
        "{%0,%1,%2,%3}, {%4,%5,%6,%7}, {%8,%9}, {%0,%1,%2,%3};"
        : "+f"(d[0]), "+f"(d[1]), "+f"(d[2]), "+f"(d[3])
        : "r"(a[0]), "r"(a[1]), "r"(a[2]), "r"(a[3]), "r"(b[0]), "r"(b[1]));
}

// ---------------- 0) dtype detection ----------------
__global__ void detect_dtype_kernel(const void* edge_index) {
    if (threadIdx.x == 0 && blockIdx.x == 0) {
        const long long* p = (const long long*)edge_index;
        int ok = 1;
        for (int i = 0; i < 64; i++) {
            long long v = p[i];
            if (v < 0 || v >= N_NODES) { ok = 0; break; }
        }
        g_is64 = ok;
    }
}

// ---------------- 1) c vectors: c_src[k][h] = sum_d W[k, h*200+d] * a_src[h][d] -----
__global__ void cvec_kernel(const float* __restrict__ Wm,
                            const float* __restrict__ a_src,
                            const float* __restrict__ a_dst) {
    int wid  = (blockIdx.x * blockDim.x + threadIdx.x) >> 5;
    int lane = threadIdx.x & 31;
    if (wid >= IN_DIM * HEADS) return;
    int k = wid >> 2, h = wid & 3;
    const float* wrow = Wm + (size_t)k * HID + h * OUT_DIM;
    const float* as = a_src + h * OUT_DIM;
    const float* ad = a_dst + h * OUT_DIM;
    float cs = 0.f, cd = 0.f;
    for (int d = lane; d < OUT_DIM; d += 32) {
        float w = wrow[d];
        cs = fmaf(w, as[d], cs);
        cd = fmaf(w, ad[d], cd);
    }
    cs = warp_reduce(cs);
    cd = warp_reduce(cd);
    if (lane == 0) { g_csrc[k * 4 + h] = cs; g_cdst[k * 4 + h] = cd; }
}

// ---------------- 2) init: ssrc/sdst/denom = 0, cnt = 0 ----------------
__global__ void init_kernel() {
    int tid = blockIdx.x * blockDim.x + threadIdx.x;
    if (tid < N_NODES * HEADS) {
        g_denom[tid] = 0.0f;
        g_ssrc[tid]  = 0.0f;
        g_sdst[tid]  = 0.0f;
    }
    if (tid < N_NODES) g_cnt[tid] = 0;
}

// ---------------- 3a) split A into fp16 hi/lo + fused s_src/s_dst ----------------
// thread t owns k = 4t..4t+3 for ALL nodes (c stays in registers).
__global__ void __launch_bounds__(256) split_a_kernel(const float* __restrict__ A) {
    const int t = threadIdx.x;
    const int lane = t & 31;
    float4 cs[4], cd[4];
    #pragma unroll
    for (int q = 0; q < 4; q++) {
        cs[q] = ((const float4*)g_csrc)[t * 4 + q];
        cd[q] = ((const float4*)g_cdst)[t * 4 + q];
    }
    for (int n = blockIdx.x; n < N_NODES; n += gridDim.x) {
        float4 a = ((const float4*)(A + (size_t)n * IN_DIM))[t];
        float av[4] = {a.x, a.y, a.z, a.w};
        float ss0 = 0.f, ss1 = 0.f, ss2 = 0.f, ss3 = 0.f;
        float sd0 = 0.f, sd1 = 0.f, sd2 = 0.f, sd3 = 0.f;
        #pragma unroll
        for (int q = 0; q < 4; q++) {
            ss0 = fmaf(av[q], cs[q].x, ss0); ss1 = fmaf(av[q], cs[q].y, ss1);
            ss2 = fmaf(av[q], cs[q].z, ss2); ss3 = fmaf(av[q], cs[q].w, ss3);
            sd0 = fmaf(av[q], cd[q].x, sd0); sd1 = fmaf(av[q], cd[q].y, sd1);
            sd2 = fmaf(av[q], cd[q].z, sd2); sd3 = fmaf(av[q], cd[q].w, sd3);
        }
        // fp16 split store (coalesced: 8B per thread per array)
        __half hx = __float2half(a.x), hy = __float2half(a.y);
        __half hz = __float2half(a.z), hw = __float2half(a.w);
        __half lx = __float2half(a.x - __half2float(hx));
        __half ly = __float2half(a.y - __half2float(hy));
        __half lz = __float2half(a.z - __half2float(hz));
        __half lw = __float2half(a.w - __half2float(hw));
        __half2* ph = (__half2*)(g_Ah + (size_t)n * IN_DIM) + t * 2;
        __half2* pl = (__half2*)(g_Al + (size_t)n * IN_DIM) + t * 2;
        ph[0] = __halves2half2(hx, hy); ph[1] = __halves2half2(hz, hw);
        pl[0] = __halves2half2(lx, ly); pl[1] = __halves2half2(lz, lw);
        // butterfly reduce 8 values across warp
        #pragma unroll
        for (int o = 16; o > 0; o >>= 1) {
            ss0 += __shfl_xor_sync(0xffffffffu, ss0, o);
            ss1 += __shfl_xor_sync(0xffffffffu, ss1, o);
            ss2 += __shfl_xor_sync(0xffffffffu, ss2, o);
            ss3 += __shfl_xor_sync(0xffffffffu, ss3, o);
            sd0 += __shfl_xor_sync(0xffffffffu, sd0, o);
            sd1 += __shfl_xor_sync(0xffffffffu, sd1, o);
            sd2 += __shfl_xor_sync(0xffffffffu, sd2, o);
            sd3 += __shfl_xor_sync(0xffffffffu, sd3, o);
        }
        if (lane == 0) {
            atomicAdd(&g_ssrc[n * 4 + 0], ss0);
            atomicAdd(&g_ssrc[n * 4 + 1], ss1);
            atomicAdd(&g_ssrc[n * 4 + 2], ss2);
            atomicAdd(&g_ssrc[n * 4 + 3], ss3);
            atomicAdd(&g_sdst[n * 4 + 0], sd0);
            atomicAdd(&g_sdst[n * 4 + 1], sd1);
            atomicAdd(&g_sdst[n * 4 + 2], sd2);
            atomicAdd(&g_sdst[n * 4 + 3], sd3);
        }
    }
}

// ---------------- 3b) transpose W -> fp16 Bt via smem tile ----------------
__global__ void __launch_bounds__(256) split_b_kernel(const float* __restrict__ Wm) {
    __shared__ float tile[32][33];
    const int tx = threadIdx.x;        // 0..31
    const int ty = threadIdx.y;        // 0..7
    const int k0 = blockIdx.x * 32;
    const int n0 = blockIdx.y * 32;
    #pragma unroll
    for (int j = 0; j < 4; j++) {
        int k = k0 + ty + j * 8;
        int n = n0 + tx;
        tile[ty + j * 8][tx] = (n < HID) ? Wm[(size_t)k * HID + n] : 0.0f;
    }
    __syncthreads();
    #pragma unroll
    for (int j = 0; j < 4; j++) {
        int n = n0 + ty + j * 8;
        int k = k0 + tx;
        g_Bh[(size_t)n * IN_DIM + k] = __float2half(tile[tx][ty + j * 8]);
    }
}

// ---------------- 4) HMMA GEMM: 2-pass fp16 (A exact pair, W single) ----------------
__global__ void __launch_bounds__(256) gemm_mma_kernel() {
    extern __shared__ char smem[];
    const uint32_t sbase = smem_u32(smem);
    const int t = threadIdx.x;
    const int lane = t & 31;
    const int warp = t >> 5;
    const int wm = warp >> 1;
    const int wn = warp & 1;
    const int n0 = blockIdx.x * BN;
    const int row0 = blockIdx.y * BM;

    float acc[2][4][4];
    #pragma unroll
    for (int mi = 0; mi < 2; mi++)
        #pragma unroll
        for (int nj = 0; nj < 4; nj++)
            #pragma unroll
            for (int q = 0; q < 4; q++) acc[mi][nj][q] = 0.0f;

    auto load_chunk = [&](int c, int buf) {
        #pragma unroll
        for (int i = 0; i < 2; i++) {
            int lin = i * 256 + t;
            int r = lin >> 2, seg = lin & 3;
            int gr = row0 + r; if (gr > N_NODES - 1) gr = N_NODES - 1;
            size_t go = (size_t)gr * IN_DIM + c * BK + seg * 8;
            uint32_t so = (uint32_t)(r * A_STRIDE + seg * 16);
            cp_async16(sbase + SA_OFF(buf, 0) + so, g_Ah + go);
            cp_async16(sbase + SA_OFF(buf, 1) + so, g_Al + go);
        }
        {
            int r = t >> 2, seg = t & 3;
            size_t go = (size_t)(n0 + r) * IN_DIM + c * BK + seg * 8;
            uint32_t so = (uint32_t)(r * A_STRIDE + seg * 16);
            cp_async16(sbase + SB_OFF(buf) + so, g_Bh + go);
        }
        cp_commit();
    };

    load_chunk(0, 0);
    load_chunk(1, 1);

    for (int c = 0; c < NCHUNK; c++) {
        if (c == NCHUNK - 1) cp_wait<0>(); else cp_wait<1>();
        __syncthreads();
        const int buf = c & 1;

        #pragma unroll
        for (int k16 = 0; k16 < BK; k16 += 16) {
            uint32_t af[2][2][4];   // [ver][mi][4]
            #pragma unroll
            for (int ver = 0; ver < 2; ver++)
                #pragma unroll
                for (int mi = 0; mi < 2; mi++) {
                    int r = wm * 32 + mi * 16 + (lane & 7) + ((lane >> 3) & 1) * 8;
                    int colB = (k16 + (lane >> 4) * 8) * 2;
                    ldm_x4(af[ver][mi], sbase + SA_OFF(buf, ver) + r * A_STRIDE + colB);
                }
            uint32_t bf[4][2];      // [nj][2]
            #pragma unroll
            for (int pr = 0; pr < 2; pr++) {
                uint32_t r4[4];
                int n = wn * 32 + pr * 16 + ((lane >> 4) & 1) * 8 + (lane & 7);
                int colB = (k16 + ((lane >> 3) & 1) * 8) * 2;
                ldm_x4(r4, sbase + SB_OFF(buf) + n * A_STRIDE + colB);
                bf[pr * 2 + 0][0] = r4[0]; bf[pr * 2 + 0][1] = r4[1];
                bf[pr * 2 + 1][0] = r4[2]; bf[pr * 2 + 1][1] = r4[3];
            }
            // two passes: Ah*Wh + Al*Wh  (A exact as fp16 pair)
            #pragma unroll
            for (int mi = 0; mi < 2; mi++)
                #pragma unroll
                for (int nj = 0; nj < 4; nj++) {
                    mma16816(acc[mi][nj], af[0][mi], bf[nj]);
                    mma16816(acc[mi][nj], af[1][mi], bf[nj]);
                }
        }
        __syncthreads();
        if (c + 2 < NCHUNK) load_chunk(c + 2, buf);
    }

    #pragma unroll
    for (int mi = 0; mi < 2; mi++)
        #pragma unroll
        for (int nj = 0; nj < 4; nj++) {
            int tileN = n0 + wn * 32 + nj * 8;
            if (tileN >= HID) continue;
            int col = tileN + 2 * (lane & 3);
            int r0 = row0 + wm * 32 + mi * 16 + (lane >> 2);
            if (r0 < N_NODES)
                *(float2*)(g_h + (size_t)r0 * HID + col) =
                    make_float2(acc[mi][nj][0], acc[mi][nj][1]);
            int r1 = r0 + 8;
            if (r1 < N_NODES)
                *(float2*)(g_h + (size_t)r1 * HID + col) =
                    make_float2(acc[mi][nj][2], acc[mi][nj][3]);
        }
}

// ---------------- 5) rel logits ----------------
__global__ void rel_logits_kernel(const float* __restrict__ rel_feat,
                                  const float* __restrict__ a_rel) {
    int wid  = (blockIdx.x * blockDim.x + threadIdx.x) >> 5;
    int lane = threadIdx.x & 31;
    if (wid >= NUM_REL * HEADS) return;
    int r = wid >> 2, h = wid & 3;
    const float* rp = rel_feat + (size_t)r * HID + h * OUT_DIM;
    const float* ar = a_rel + h * OUT_DIM;
    float s = 0.f;
    for (int d = lane; d < OUT_DIM; d += 32) s = fmaf(rp[d], ar[d], s);
    s = warp_reduce(s);
    if (lane == 0) g_rlog[wid] = s;
}

// ---------------- 6) edge pass: logit -> leaky -> exp -> denom (+count) ----------
__global__ void edge_lse_kernel(const void* __restrict__ ei,
                                const void* __restrict__ et) {
    int idx = blockIdx.x * blockDim.x + threadIdx.x;
    if (idx >= E_EDGES * HEADS) return;
    int e = idx >> 2, h = idx & 3;
    int s = load_idx(ei, e);
    int d = load_idx(ei, E_EDGES + e);
    int r = load_idx(et, e);
    float x = g_ssrc[s * 4 + h] + g_sdst[d * 4 + h] + g_rlog[r * 4 + h];
    x = (x >= 0.f) ? x : NEG_SLOPE * x;
    float ev = expf(x);
    g_elog[idx] = ev;
    atomicAdd(&g_denom[d * 4 + h], ev);
    if (h == 0) atomicAdd(&g_cnt[d], 1);
}

// ---------------- 7) exclusive scan of counts (single CTA) ----------------
__global__ void scan_kernel() {
    __shared__ int warp_sums[32];
    __shared__ int s_base;
    const int t = threadIdx.x;
    const int lane = t & 31, wid = t >> 5;
    if (t == 0) s_base = 0;
    __syncthreads();
    const int nchunks = (N_NODES + 1023) / 1024;
    for (int ch = 0; ch < nchunks; ch++) {
        int i = ch * 1024 + t;
        int v = (i < N_NODES) ? g_cnt[i] : 0;
        int x = v;
        #pragma unroll
        for (int o = 1; o < 32; o <<= 1) {
            int y = __shfl_up_sync(0xffffffffu, x, o);
            if (lane >= o) x += y;
        }
        if (lane == 31) warp_sums[wid] = x;
        __syncthreads();
        if (wid == 0) {
            int w = warp_sums[lane];
            #pragma unroll
            for (int o = 1; o < 32; o <<= 1) {
                int y = __shfl_up_sync(0xffffffffu, w, o);
                if (lane >= o) w += y;
            }
            warp_sums[lane] = w;
        }
        __syncthreads();
        int warp_off = (wid == 0) ? 0 : warp_sums[wid - 1];
        int excl = s_base + warp_off + (x - v);
        if (i < N_NODES) { g_rowptr[i] = excl; g_cursor[i] = excl; }
        __syncthreads();
        if (t == 0) s_base += warp_sums[31];
        __syncthreads();
    }
    if (t == 0) g_rowptr[N_NODES] = s_base;
}

// ---------------- 8) CSR fill ----------------
__global__ void fill_kernel(const void* __restrict__ ei) {
    int e = blockIdx.x * blockDim.x + threadIdx.x;
    if (e >= E_EDGES) return;
    int d = load_idx(ei, E_EDGES + e);
    int pos = atomicAdd(&g_cursor[d], 1);
    g_csre[pos] = e;
}

// ---------------- 9) aggregate: warp per node, no atomics ----------------
__global__ void __launch_bounds__(256) agg_kernel(const void* __restrict__ ei) {
    int n    = (blockIdx.x * blockDim.x + threadIdx.x) >> 5;
    int lane = threadIdx.x & 31;
    if (n >= N_NODES) return;
    int rp0 = g_rowptr[n], rp1 = g_rowptr[n + 1];
    float4 dn = *(const float4*)(g_denom + n * 4);
    float r0 = (rp1 > rp0) ? 1.0f / dn.x : 0.0f;
    float r1 = (rp1 > rp0) ? 1.0f / dn.y : 0.0f;
    float r2 = (rp1 > rp0) ? 1.0f / dn.z : 0.0f;
    float r3 = (rp1 > rp0) ? 1.0f / dn.w : 0.0f;
    float4 acc[7];
    #pragma unroll
    for (int it = 0; it < 7; it++) acc[it] = make_float4(0.f, 0.f, 0.f, 0.f);

    for (int j = rp0; j < rp1; j++) {
        int e = g_csre[j];
        int s = load_idx(ei, e);
        float4 ev = *(const float4*)(g_elog + e * 4);
        float a0 = ev.x * r0, a1 = ev.y * r1, a2 = ev.z * r2, a3 = ev.w * r3;
        const float4* hs = (const float4*)(g_h + (size_t)s * HID);
        #pragma unroll
        for (int it = 0; it < 7; it++) {
            int c = lane + it * 32;
            if (c < HID / 4) {
                float a = (c < 50) ? a0 : (c < 100) ? a1 : (c < 150) ? a2 : a3;
                float4 v = hs[c];
                acc[it].x = fmaf(a, v.x, acc[it].x);
                acc[it].y = fmaf(a, v.y, acc[it].y);
                acc[it].z = fmaf(a, v.z, acc[it].z);
                acc[it].w = fmaf(a, v.w, acc[it].w);
            }
        }
    }
    float4* op = (float4*)(g_out + (size_t)n * HID);
    #pragma unroll
    for (int it = 0; it < 7; it++) {
        int c = lane + it * 32;
        if (c < HID / 4) op[c] = acc[it];
    }
}

// ---------------- 10) DistMult ----------------
__global__ void distmult_kernel(const float* __restrict__ bias,
                                const float* __restrict__ rel_emb,
                                const void* __restrict__ si,
                                const void* __restrict__ ri,
                                const void* __restrict__ di,
                                float* __restrict__ out) {
    int wid  = (blockIdx.x * blockDim.x + threadIdx.x) >> 5;
    int lane = threadIdx.x & 31;
    if (wid >= BATCH) return;
    int s = load_idx(si, wid);
    int r = load_idx(ri, wid);
    int d = load_idx(di, wid);
    const float* ps = g_out + (size_t)s * HID;
    const float* pd = g_out + (size_t)d * HID;
    const float* pr = rel_emb + (size_t)r * HID;
    float acc = 0.f;
    for (int k = lane; k < HID; k += 32) {
        float b = bias[k];
        acc = fmaf((ps[k] + b) * pr[k], (pd[k] + b), acc);
    }
    acc = warp_reduce(acc);
    if (lane == 0) out[wid] = acc;
}

// ---------------- launch ----------------
extern "C" void kernel_launch(void* const* d_in, const int* in_sizes, int n_in,
                              void* d_out, int out_size) {
    const float* node_emb   = (const float*)d_in[0];
    const float* Wm         = (const float*)d_in[1];
    const float* bias       = (const float*)d_in[2];
    const float* a_src      = (const float*)d_in[3];
    const float* a_dst      = (const float*)d_in[4];
    const float* a_rel      = (const float*)d_in[5];
    const float* rel_feat   = (const float*)d_in[6];
    const float* rel_emb    = (const float*)d_in[7];
    const void*  edge_index = d_in[8];
    const void*  edge_type  = d_in[9];
    const void*  src_ids    = d_in[10];
    const void*  rel_ids    = d_in[11];
    const void*  dst_ids    = d_in[12];
    float* out = (float*)d_out;

    cudaFuncSetAttribute(gemm_mma_kernel,
                         cudaFuncAttributeMaxDynamicSharedMemorySize, SM_TOT);

    detect_dtype_kernel<<<1, 32>>>(edge_index);
    cvec_kernel<<<(IN_DIM * HEADS * 32 + 255) / 256, 256>>>(Wm, a_src, a_dst);
    rel_logits_kernel<<<(NUM_REL * HEADS * 32 + 255) / 256, 256>>>(rel_feat, a_rel);
    init_kernel<<<(N_NODES * HEADS + 255) / 256, 256>>>();

    split_a_kernel<<<592, 256>>>(node_emb);
    {
        dim3 bgrid(IN_DIM / 32, PAD_N / 32);
        split_b_kernel<<<bgrid, dim3(32, 8)>>>(Wm);
    }

    dim3 ggrid(NT_N, NT_M);
    gemm_mma_kernel<<<ggrid, 256, SM_TOT>>>();

    edge_lse_kernel<<<(E_EDGES * HEADS + 255) / 256, 256>>>(edge_index, edge_type);
    scan_kernel<<<1, 1024>>>();
    fill_kernel<<<(E_EDGES + 255) / 256, 256>>>(edge_index);
    agg_kernel<<<(N_NODES * 32 + 255) / 256, 256>>>(edge_index);

    distmult_kernel<<<(BATCH * 32 + 255) / 256, 256>>>(bias, rel_emb,
                                                       src_ids, rel_ids, dst_ids, out);
}

// round 9
// speedup vs baseline: 2.5255x; 1.6721x over previous
#include <cuda_runtime.h>
#include <cuda_fp16.h>
#include <cfloat>
#include <cstdint>

#define N_NODES 50000
#define IN_DIM  1024
#define E_EDGES 100000
#define NUM_REL 40
#define HEADS   4
#define OUT_DIM 200
#define HID     800
#define BATCH   8192
#define NEG_SLOPE 0.2f

#define BM 128
#define BN 64
#define BK 32
#define NCHUNK (IN_DIM / BK)            // 32
#define NT_M ((N_NODES + BM - 1) / BM)  // 391 (max tiles; CTAs early-exit past len)
#define NT_N 13                         // ceil(800/64)
#define PAD_N (NT_N * BN)               // 832

#define A_STRIDE 80
#define A_VER_SZ (128 * A_STRIDE)       // 10240
#define B_VER_SZ (64 * A_STRIDE)        // 5120
#define SA_OFF(buf, ver) ((buf) * (2 * A_VER_SZ) + (ver) * A_VER_SZ)
#define SB_OFF(buf)      (4 * A_VER_SZ + (buf) * B_VER_SZ)
#define SM_TOT (4 * A_VER_SZ + 2 * B_VER_SZ)   // 51200

#define SPLITA_BLOCKS 592
#define SPLITB_BLOCKS ((IN_DIM / 32) * (PAD_N / 32))   // 32*26 = 832

// ---------------- scratch (device globals) ----------------
__device__ __align__(16) float g_h  [(size_t)N_NODES * HID];   // compacted h rows
__device__ __align__(16) float g_out[(size_t)N_NODES * HID];
__device__ __align__(16) __half g_Ah[(size_t)N_NODES * IN_DIM];
__device__ __align__(16) __half g_Al[(size_t)N_NODES * IN_DIM];
__device__ __align__(16) __half g_Bh[(size_t)PAD_N * IN_DIM];   // W^T, K-major, fp16
__device__ __align__(16) float g_csrc[IN_DIM * HEADS];
__device__ __align__(16) float g_cdst[IN_DIM * HEADS];
__device__ __align__(16) float g_ssrc  [N_NODES * HEADS];
__device__ __align__(16) float g_sdst  [N_NODES * HEADS];
__device__ float g_rlog  [NUM_REL * HEADS];
__device__ __align__(16) float g_denom [N_NODES * HEADS];
__device__ __align__(16) float g_elog  [E_EDGES * HEADS];
__device__ int   g_cnt   [N_NODES];
__device__ int   g_rowptr[N_NODES + 1];
__device__ int   g_cursor[N_NODES];
__device__ int   g_csre  [E_EDGES];
__device__ unsigned char g_need_out[N_NODES];
__device__ unsigned char g_need_h  [N_NODES];
__device__ int   g_hidx  [N_NODES];
__device__ int   g_hlist [N_NODES];
__device__ int   g_hcount;
__device__ int   g_is64;

// ---------------- helpers ----------------
__device__ __forceinline__ int load_idx(const void* p, int i) {
    if (g_is64) return (int)((const long long*)p)[i];
    return ((const int*)p)[i];
}
__device__ __forceinline__ float warp_reduce(float v) {
    #pragma unroll
    for (int o = 16; o > 0; o >>= 1) v += __shfl_down_sync(0xffffffffu, v, o);
    return v;
}
__device__ __forceinline__ uint32_t smem_u32(const void* p) {
    uint32_t a;
    asm("{ .reg .u64 t; cvta.to.shared.u64 t, %1; cvt.u32.u64 %0, t; }" : "=r"(a) : "l"(p));
    return a;
}
__device__ __forceinline__ void cp_async16(uint32_t s, const void* g) {
    asm volatile("cp.async.cg.shared.global [%0], [%1], 16;" :: "r"(s), "l"(g));
}
__device__ __forceinline__ void cp_commit() {
    asm volatile("cp.async.commit_group;" ::: "memory");
}
template<int NN> __device__ __forceinline__ void cp_wait() {
    asm volatile("cp.async.wait_group %0;" :: "n"(NN) : "memory");
}
__device__ __forceinline__ void ldm_x4(uint32_t* r, uint32_t addr) {
    asm volatile("ldmatrix.sync.aligned.m8n8.x4.shared.b16 {%0,%1,%2,%3}, [%4];"
                 : "=r"(r[0]), "=r"(r[1]), "=r"(r[2]), "=r"(r[3]) : "r"(addr));
}
__device__ __forceinline__ void mma16816(float* d, const uint32_t* a, const uint32_t* b) {
    asm volatile(
        "mma.sync.aligned.m16n8k16.row.col.f32.f16.f16.f32 "
        "{%0,%1,%2,%3}, {%4,%5,%6,%7}, {%8,%9}, {%0,%1,%2,%3};"
        : "+f"(d[0]), "+f"(d[1]), "+f"(d[2]), "+f"(d[3])
        : "r"(a[0]), "r"(a[1]), "r"(a[2]), "r"(a[3]), "r"(b[0]), "r"(b[1]));
}

// ---------------- 0) init everything ----------------
__global__ void init_kernel() {
    int tid = blockIdx.x * blockDim.x + threadIdx.x;
    if (tid < N_NODES * HEADS) {
        g_denom[tid] = 0.0f;
        g_ssrc[tid]  = 0.0f;
        g_sdst[tid]  = 0.0f;
    }
    if (tid < N_NODES) {
        g_cnt[tid] = 0;
        g_need_out[tid] = 0;
        g_need_h[tid]   = 0;
    }
    if (tid == 0) g_hcount = 0;
}

// ---------------- 1) dtype detection ----------------
__global__ void detect_dtype_kernel(const void* edge_index) {
    if (threadIdx.x == 0 && blockIdx.x == 0) {
        const long long* p = (const long long*)edge_index;
        int ok = 1;
        for (int i = 0; i < 64; i++) {
            long long v = p[i];
            if (v < 0 || v >= N_NODES) { ok = 0; break; }
        }
        g_is64 = ok;
    }
}

// ---------------- 2) mark needed output nodes (distmult endpoints) ----------------
__global__ void mark_dst_kernel(const void* __restrict__ si, const void* __restrict__ di) {
    int i = blockIdx.x * blockDim.x + threadIdx.x;
    if (i < BATCH)            g_need_out[load_idx(si, i)] = 1;
    else if (i < 2 * BATCH)   g_need_out[load_idx(di, i - BATCH)] = 1;
}

// ---------------- 3) mark needed h rows (sources of in-edges of needed nodes) ----
__global__ void mark_src_kernel(const void* __restrict__ ei) {
    int e = blockIdx.x * blockDim.x + threadIdx.x;
    if (e >= E_EDGES) return;
    int d = load_idx(ei, E_EDGES + e);
    if (g_need_out[d]) {
        int s = load_idx(ei, e);
        g_need_h[s] = 1;
    }
}

// ---------------- 4) compact needed h rows into a list ----------------
__global__ void compact_kernel() {
    int n = blockIdx.x * blockDim.x + threadIdx.x;
    if (n >= N_NODES) return;
    if (g_need_h[n]) {
        int p = atomicAdd(&g_hcount, 1);
        g_hlist[p] = n;
        g_hidx[n] = p;
    }
}

// ---------------- 5) c vectors ----------------
__global__ void cvec_kernel(const float* __restrict__ Wm,
                            const float* __restrict__ a_src,
                            const float* __restrict__ a_dst) {
    int wid  = (blockIdx.x * blockDim.x + threadIdx.x) >> 5;
    int lane = threadIdx.x & 31;
    if (wid >= IN_DIM * HEADS) return;
    int k = wid >> 2, h = wid & 3;
    const float* wrow = Wm + (size_t)k * HID + h * OUT_DIM;
    const float* as = a_src + h * OUT_DIM;
    const float* ad = a_dst + h * OUT_DIM;
    float cs = 0.f, cd = 0.f;
    for (int d = lane; d < OUT_DIM; d += 32) {
        float w = wrow[d];
        cs = fmaf(w, as[d], cs);
        cd = fmaf(w, ad[d], cd);
    }
    cs = warp_reduce(cs);
    cd = warp_reduce(cd);
    if (lane == 0) { g_csrc[k * 4 + h] = cs; g_cdst[k * 4 + h] = cd; }
}

// ---------------- 6) rel logits ----------------
__global__ void rel_logits_kernel(const float* __restrict__ rel_feat,
                                  const float* __restrict__ a_rel) {
    int wid  = (blockIdx.x * blockDim.x + threadIdx.x) >> 5;
    int lane = threadIdx.x & 31;
    if (wid >= NUM_REL * HEADS) return;
    int r = wid >> 2, h = wid & 3;
    const float* rp = rel_feat + (size_t)r * HID + h * OUT_DIM;
    const float* ar = a_rel + h * OUT_DIM;
    float s = 0.f;
    for (int d = lane; d < OUT_DIM; d += 32) s = fmaf(rp[d], ar[d], s);
    s = warp_reduce(s);
    if (lane == 0) g_rlog[wid] = s;
}

// ---------------- 7) fused split: A->fp16 pair + ssrc/sdst, and W->fp16 B^T -------
__global__ void __launch_bounds__(256) split_fused_kernel(const float* __restrict__ A,
                                                          const float* __restrict__ Wm) {
    const int bid = blockIdx.x;
    if (bid < SPLITA_BLOCKS) {
        const int t = threadIdx.x;
        const int lane = t & 31;
        float4 cs[4], cd[4];
        #pragma unroll
        for (int q = 0; q < 4; q++) {
            cs[q] = ((const float4*)g_csrc)[t * 4 + q];
            cd[q] = ((const float4*)g_cdst)[t * 4 + q];
        }
        for (int n = bid; n < N_NODES; n += SPLITA_BLOCKS) {
            float4 a = ((const float4*)(A + (size_t)n * IN_DIM))[t];
            float av[4] = {a.x, a.y, a.z, a.w};
            float ss0 = 0.f, ss1 = 0.f, ss2 = 0.f, ss3 = 0.f;
            float sd0 = 0.f, sd1 = 0.f, sd2 = 0.f, sd3 = 0.f;
            #pragma unroll
            for (int q = 0; q < 4; q++) {
                ss0 = fmaf(av[q], cs[q].x, ss0); ss1 = fmaf(av[q], cs[q].y, ss1);
                ss2 = fmaf(av[q], cs[q].z, ss2); ss3 = fmaf(av[q], cs[q].w, ss3);
                sd0 = fmaf(av[q], cd[q].x, sd0); sd1 = fmaf(av[q], cd[q].y, sd1);
                sd2 = fmaf(av[q], cd[q].z, sd2); sd3 = fmaf(av[q], cd[q].w, sd3);
            }
            __half hx = __float2half(a.x), hy = __float2half(a.y);
            __half hz = __float2half(a.z), hw = __float2half(a.w);
            __half lx = __float2half(a.x - __half2float(hx));
            __half ly = __float2half(a.y - __half2float(hy));
            __half lz = __float2half(a.z - __half2float(hz));
            __half lw = __float2half(a.w - __half2float(hw));
            __half2* ph = (__half2*)(g_Ah + (size_t)n * IN_DIM) + t * 2;
            __half2* pl = (__half2*)(g_Al + (size_t)n * IN_DIM) + t * 2;
            ph[0] = __halves2half2(hx, hy); ph[1] = __halves2half2(hz, hw);
            pl[0] = __halves2half2(lx, ly); pl[1] = __halves2half2(lz, lw);
            #pragma unroll
            for (int o = 16; o > 0; o >>= 1) {
                ss0 += __shfl_xor_sync(0xffffffffu, ss0, o);
                ss1 += __shfl_xor_sync(0xffffffffu, ss1, o);
                ss2 += __shfl_xor_sync(0xffffffffu, ss2, o);
                ss3 += __shfl_xor_sync(0xffffffffu, ss3, o);
                sd0 += __shfl_xor_sync(0xffffffffu, sd0, o);
                sd1 += __shfl_xor_sync(0xffffffffu, sd1, o);
                sd2 += __shfl_xor_sync(0xffffffffu, sd2, o);
                sd3 += __shfl_xor_sync(0xffffffffu, sd3, o);
            }
            if (lane == 0) {
                atomicAdd(&g_ssrc[n * 4 + 0], ss0);
                atomicAdd(&g_ssrc[n * 4 + 1], ss1);
                atomicAdd(&g_ssrc[n * 4 + 2], ss2);
                atomicAdd(&g_ssrc[n * 4 + 3], ss3);
                atomicAdd(&g_sdst[n * 4 + 0], sd0);
                atomicAdd(&g_sdst[n * 4 + 1], sd1);
                atomicAdd(&g_sdst[n * 4 + 2], sd2);
                atomicAdd(&g_sdst[n * 4 + 3], sd3);
            }
        }
    } else {
        // B transpose path
        __shared__ float tile[32][33];
        const int b = bid - SPLITA_BLOCKS;
        const int tx = threadIdx.x & 31;
        const int ty = threadIdx.x >> 5;       // 0..7
        const int k0 = (b % (IN_DIM / 32)) * 32;
        const int n0 = (b / (IN_DIM / 32)) * 32;
        #pragma unroll
        for (int j = 0; j < 4; j++) {
            int k = k0 + ty + j * 8;
            int n = n0 + tx;
            tile[ty + j * 8][tx] = (n < HID) ? Wm[(size_t)k * HID + n] : 0.0f;
        }
        __syncthreads();
        #pragma unroll
        for (int j = 0; j < 4; j++) {
            int n = n0 + ty + j * 8;
            int k = k0 + tx;
            g_Bh[(size_t)n * IN_DIM + k] = __float2half(tile[tx][ty + j * 8]);
        }
    }
}

// ---------------- 8) HMMA GEMM over compacted rows ----------------
__global__ void __launch_bounds__(256) gemm_mma_kernel() {
    __shared__ int rowlist[BM];
    const int len = g_hcount;
    const int mt0 = blockIdx.y * BM;
    if (mt0 >= len) return;

    extern __shared__ char smem[];
    const uint32_t sbase = smem_u32(smem);
    const int t = threadIdx.x;
    const int lane = t & 31;
    const int warp = t >> 5;
    const int wm = warp >> 1;
    const int wn = warp & 1;
    const int n0 = blockIdx.x * BN;

    if (t < BM) {
        int rr = mt0 + t;
        rowlist[t] = g_hlist[rr < len ? rr : len - 1];
    }
    __syncthreads();

    float acc[2][4][4];
    #pragma unroll
    for (int mi = 0; mi < 2; mi++)
        #pragma unroll
        for (int nj = 0; nj < 4; nj++)
            #pragma unroll
            for (int q = 0; q < 4; q++) acc[mi][nj][q] = 0.0f;

    auto load_chunk = [&](int c, int buf) {
        #pragma unroll
        for (int i = 0; i < 2; i++) {
            int lin = i * 256 + t;
            int r = lin >> 2, seg = lin & 3;
            int node = rowlist[r];
            size_t go = (size_t)node * IN_DIM + c * BK + seg * 8;
            uint32_t so = (uint32_t)(r * A_STRIDE + seg * 16);
            cp_async16(sbase + SA_OFF(buf, 0) + so, g_Ah + go);
            cp_async16(sbase + SA_OFF(buf, 1) + so, g_Al + go);
        }
        {
            int r = t >> 2, seg = t & 3;
            size_t go = (size_t)(n0 + r) * IN_DIM + c * BK + seg * 8;
            uint32_t so = (uint32_t)(r * A_STRIDE + seg * 16);
            cp_async16(sbase + SB_OFF(buf) + so, g_Bh + go);
        }
        cp_commit();
    };

    load_chunk(0, 0);
    load_chunk(1, 1);

    for (int c = 0; c < NCHUNK; c++) {
        if (c == NCHUNK - 1) cp_wait<0>(); else cp_wait<1>();
        __syncthreads();
        const int buf = c & 1;

        #pragma unroll
        for (int k16 = 0; k16 < BK; k16 += 16) {
            uint32_t af[2][2][4];
            #pragma unroll
            for (int ver = 0; ver < 2; ver++)
                #pragma unroll
                for (int mi = 0; mi < 2; mi++) {
                    int r = wm * 32 + mi * 16 + (lane & 7) + ((lane >> 3) & 1) * 8;
                    int colB = (k16 + (lane >> 4) * 8) * 2;
                    ldm_x4(af[ver][mi], sbase + SA_OFF(buf, ver) + r * A_STRIDE + colB);
                }
            uint32_t bf[4][2];
            #pragma unroll
            for (int pr = 0; pr < 2; pr++) {
                uint32_t r4[4];
                int n = wn * 32 + pr * 16 + ((lane >> 4) & 1) * 8 + (lane & 7);
                int colB = (k16 + ((lane >> 3) & 1) * 8) * 2;
                ldm_x4(r4, sbase + SB_OFF(buf) + n * A_STRIDE + colB);
                bf[pr * 2 + 0][0] = r4[0]; bf[pr * 2 + 0][1] = r4[1];
                bf[pr * 2 + 1][0] = r4[2]; bf[pr * 2 + 1][1] = r4[3];
            }
            #pragma unroll
            for (int mi = 0; mi < 2; mi++)
                #pragma unroll
                for (int nj = 0; nj < 4; nj++) {
                    mma16816(acc[mi][nj], af[0][mi], bf[nj]);
                    mma16816(acc[mi][nj], af[1][mi], bf[nj]);
                }
        }
        __syncthreads();
        if (c + 2 < NCHUNK) load_chunk(c + 2, buf);
    }

    // epilogue: store to compacted h rows
    #pragma unroll
    for (int mi = 0; mi < 2; mi++)
        #pragma unroll
        for (int nj = 0; nj < 4; nj++) {
            int tileN = n0 + wn * 32 + nj * 8;
            if (tileN >= HID) continue;
            int col = tileN + 2 * (lane & 3);
            int lr0 = wm * 32 + mi * 16 + (lane >> 2);
            if (mt0 + lr0 < len)
                *(float2*)(g_h + (size_t)(mt0 + lr0) * HID + col) =
                    make_float2(acc[mi][nj][0], acc[mi][nj][1]);
            if (mt0 + lr0 + 8 < len)
                *(float2*)(g_h + (size_t)(mt0 + lr0 + 8) * HID + col) =
                    make_float2(acc[mi][nj][2], acc[mi][nj][3]);
        }
}

// ---------------- 9) edge pass (gated to needed destinations) ----------------
__global__ void edge_lse_kernel(const void* __restrict__ ei,
                                const void* __restrict__ et) {
    int idx = blockIdx.x * blockDim.x + threadIdx.x;
    if (idx >= E_EDGES * HEADS) return;
    int e = idx >> 2, h = idx & 3;
    int d = load_idx(ei, E_EDGES + e);
    if (!g_need_out[d]) return;
    int s = load_idx(ei, e);
    int r = load_idx(et, e);
    float x = g_ssrc[s * 4 + h] + g_sdst[d * 4 + h] + g_rlog[r * 4 + h];
    x = (x >= 0.f) ? x : NEG_SLOPE * x;
    float ev = expf(x);
    g_elog[idx] = ev;
    atomicAdd(&g_denom[d * 4 + h], ev);
    if (h == 0) atomicAdd(&g_cnt[d], 1);
}

// ---------------- 10) exclusive scan of counts (single CTA) ----------------
__global__ void scan_kernel() {
    __shared__ int warp_sums[32];
    __shared__ int s_base;
    const int t = threadIdx.x;
    const int lane = t & 31, wid = t >> 5;
    if (t == 0) s_base = 0;
    __syncthreads();
    const int nchunks = (N_NODES + 1023) / 1024;
    for (int ch = 0; ch < nchunks; ch++) {
        int i = ch * 1024 + t;
        int v = (i < N_NODES) ? g_cnt[i] : 0;
        int x = v;
        #pragma unroll
        for (int o = 1; o < 32; o <<= 1) {
            int y = __shfl_up_sync(0xffffffffu, x, o);
            if (lane >= o) x += y;
        }
        if (lane == 31) warp_sums[wid] = x;
        __syncthreads();
        if (wid == 0) {
            int w = warp_sums[lane];
            #pragma unroll
            for (int o = 1; o < 32; o <<= 1) {
                int y = __shfl_up_sync(0xffffffffu, w, o);
                if (lane >= o) w += y;
            }
            warp_sums[lane] = w;
        }
        __syncthreads();
        int warp_off = (wid == 0) ? 0 : warp_sums[wid - 1];
        int excl = s_base + warp_off + (x - v);
        if (i < N_NODES) { g_rowptr[i] = excl; g_cursor[i] = excl; }
        __syncthreads();
        if (t == 0) s_base += warp_sums[31];
        __syncthreads();
    }
    if (t == 0) g_rowptr[N_NODES] = s_base;
}

// ---------------- 11) CSR fill (gated) ----------------
__global__ void fill_kernel(const void* __restrict__ ei) {
    int e = blockIdx.x * blockDim.x + threadIdx.x;
    if (e >= E_EDGES) return;
    int d = load_idx(ei, E_EDGES + e);
    if (!g_need_out[d]) return;
    int pos = atomicAdd(&g_cursor[d], 1);
    g_csre[pos] = e;
}

// ---------------- 12) aggregate (needed nodes only; compacted h) ----------------
__global__ void __launch_bounds__(256) agg_kernel(const void* __restrict__ ei) {
    int n    = (blockIdx.x * blockDim.x + threadIdx.x) >> 5;
    int lane = threadIdx.x & 31;
    if (n >= N_NODES) return;
    if (!g_need_out[n]) return;
    int rp0 = g_rowptr[n], rp1 = g_rowptr[n + 1];
    float4 dn = *(const float4*)(g_denom + n * 4);
    float r0 = (rp1 > rp0) ? 1.0f / dn.x : 0.0f;
    float r1 = (rp1 > rp0) ? 1.0f / dn.y : 0.0f;
    float r2 = (rp1 > rp0) ? 1.0f / dn.z : 0.0f;
    float r3 = (rp1 > rp0) ? 1.0f / dn.w : 0.0f;
    float4 acc[7];
    #pragma unroll
    for (int it = 0; it < 7; it++) acc[it] = make_float4(0.f, 0.f, 0.f, 0.f);

    for (int j = rp0; j < rp1; j++) {
        int e = g_csre[j];
        int s = load_idx(ei, e);
        int hrow = g_hidx[s];
        float4 ev = *(const float4*)(g_elog + e * 4);
        float a0 = ev.x * r0, a1 = ev.y * r1, a2 = ev.z * r2, a3 = ev.w * r3;
        const float4* hs = (const float4*)(g_h + (size_t)hrow * HID);
        #pragma unroll
        for (int it = 0; it < 7; it++) {
            int c = lane + it * 32;
            if (c < HID / 4) {
                float a = (c < 50) ? a0 : (c < 100) ? a1 : (c < 150) ? a2 : a3;
                float4 v = hs[c];
                acc[it].x = fmaf(a, v.x, acc[it].x);
                acc[it].y = fmaf(a, v.y, acc[it].y);
                acc[it].z = fmaf(a, v.z, acc[it].z);
                acc[it].w = fmaf(a, v.w, acc[it].w);
            }
        }
    }
    float4* op = (float4*)(g_out + (size_t)n * HID);
    #pragma unroll
    for (int it = 0; it < 7; it++) {
        int c = lane + it * 32;
        if (c < HID / 4) op[c] = acc[it];
    }
}

// ---------------- 13) DistMult ----------------
__global__ void distmult_kernel(const float* __restrict__ bias,
                                const float* __restrict__ rel_emb,
                                const void* __restrict__ si,
                                const void* __restrict__ ri,
                                const void* __restrict__ di,
                                float* __restrict__ out) {
    int wid  = (blockIdx.x * blockDim.x + threadIdx.x) >> 5;
    int lane = threadIdx.x & 31;
    if (wid >= BATCH) return;
    int s = load_idx(si, wid);
    int r = load_idx(ri, wid);
    int d = load_idx(di, wid);
    const float* ps = g_out + (size_t)s * HID;
    const float* pd = g_out + (size_t)d * HID;
    const float* pr = rel_emb + (size_t)r * HID;
    float acc = 0.f;
    for (int k = lane; k < HID; k += 32) {
        float b = bias[k];
        acc = fmaf((ps[k] + b) * pr[k], (pd[k] + b), acc);
    }
    acc = warp_reduce(acc);
    if (lane == 0) out[wid] = acc;
}

// ---------------- launch ----------------
extern "C" void kernel_launch(void* const* d_in, const int* in_sizes, int n_in,
                              void* d_out, int out_size) {
    const float* node_emb   = (const float*)d_in[0];
    const float* Wm         = (const float*)d_in[1];
    const float* bias       = (const float*)d_in[2];
    const float* a_src      = (const float*)d_in[3];
    const float* a_dst      = (const float*)d_in[4];
    const float* a_rel      = (const float*)d_in[5];
    const float* rel_feat   = (const float*)d_in[6];
    const float* rel_emb    = (const float*)d_in[7];
    const void*  edge_index = d_in[8];
    const void*  edge_type  = d_in[9];
    const void*  src_ids    = d_in[10];
    const void*  rel_ids    = d_in[11];
    const void*  dst_ids    = d_in[12];
    float* out = (float*)d_out;

    cudaFuncSetAttribute(gemm_mma_kernel,
                         cudaFuncAttributeMaxDynamicSharedMemorySize, SM_TOT);

    init_kernel<<<(N_NODES * HEADS + 255) / 256, 256>>>();
    detect_dtype_kernel<<<1, 32>>>(edge_index);
    mark_dst_kernel<<<(2 * BATCH + 255) / 256, 256>>>(src_ids, dst_ids);
    mark_src_kernel<<<(E_EDGES + 255) / 256, 256>>>(edge_index);
    compact_kernel<<<(N_NODES + 255) / 256, 256>>>();

    cvec_kernel<<<(IN_DIM * HEADS * 32 + 255) / 256, 256>>>(Wm, a_src, a_dst);
    rel_logits_kernel<<<(NUM_REL * HEADS * 32 + 255) / 256, 256>>>(rel_feat, a_rel);

    split_fused_kernel<<<SPLITA_BLOCKS + SPLITB_BLOCKS, 256>>>(node_emb, Wm);

    dim3 ggrid(NT_N, NT_M);
    gemm_mma_kernel<<<ggrid, 256, SM_TOT>>>();

    edge_lse_kernel<<<(E_EDGES * HEADS + 255) / 256, 256>>>(edge_index, edge_type);
    scan_kernel<<<1, 1024>>>();
    fill_kernel<<<(E_EDGES + 255) / 256, 256>>>(edge_index);
    agg_kernel<<<(N_NODES * 32 + 255) / 256, 256>>>(edge_index);

    distmult_kernel<<<(BATCH * 32 + 255) / 256, 256>>>(bias, rel_emb,
                                                       src_ids, rel_ids, dst_ids, out);
}

// round 10
// speedup vs baseline: 3.5409x; 1.4021x over previous
#include <cuda_runtime.h>
#include <cuda_fp16.h>
#include <cfloat>
#include <cstdint>

#define N_NODES 50000
#define IN_DIM  1024
#define E_EDGES 100000
#define NUM_REL 40
#define HEADS   4
#define OUT_DIM 200
#define HID     800
#define BATCH   8192
#define NEG_SLOPE 0.2f

#define BM 128
#define BN 64
#define BK 32
#define NCHUNK (IN_DIM / BK)            // 32
#define NT_M ((N_NODES + BM - 1) / BM)  // 391 (max tiles; CTAs early-exit past len)
#define NT_N 13                         // ceil(800/64)
#define PAD_N (NT_N * BN)               // 832

#define A_STRIDE 80
#define A_VER_SZ (128 * A_STRIDE)       // 10240
#define B_VER_SZ (64 * A_STRIDE)        // 5120
#define SA_OFF(buf) ((buf) * A_VER_SZ)
#define SB_OFF(buf) (2 * A_VER_SZ + (buf) * B_VER_SZ)
#define SM_TOT (2 * A_VER_SZ + 2 * B_VER_SZ)   // 30720

#define SPLITA_BLOCKS 592
#define SPLITB_BLOCKS ((IN_DIM / 32) * (PAD_N / 32))   // 832

// ---------------- scratch (device globals) ----------------
__device__ __align__(16) float g_h  [(size_t)N_NODES * HID];   // compacted h rows
__device__ __align__(16) float g_out[(size_t)N_NODES * HID];
__device__ __align__(16) __half g_Ah[(size_t)N_NODES * IN_DIM];
__device__ __align__(16) __half g_Bh[(size_t)PAD_N * IN_DIM];   // W^T, K-major, fp16
__device__ __align__(16) float g_csrc[IN_DIM * HEADS];
__device__ __align__(16) float g_cdst[IN_DIM * HEADS];
__device__ __align__(16) float g_ssrc  [N_NODES * HEADS];
__device__ __align__(16) float g_sdst  [N_NODES * HEADS];
__device__ float g_rlog  [NUM_REL * HEADS];
__device__ __align__(16) float g_denom [N_NODES * HEADS];
__device__ __align__(16) float g_elog  [E_EDGES * HEADS];
__device__ int   g_cnt   [N_NODES];
__device__ int   g_rowptr[N_NODES + 1];
__device__ int   g_cursor[N_NODES];
__device__ int   g_csre  [E_EDGES];
__device__ unsigned char g_need_out[N_NODES];
__device__ unsigned char g_need_h  [N_NODES];
__device__ int   g_hidx  [N_NODES];
__device__ int   g_hlist [N_NODES];
__device__ int   g_ulist [N_NODES];
__device__ int   g_hcount;
__device__ int   g_ucount;
__device__ int   g_is64;

// ---------------- helpers ----------------
__device__ __forceinline__ int load_idx(const void* p, int i) {
    if (g_is64) return (int)((const long long*)p)[i];
    return ((const int*)p)[i];
}
__device__ __forceinline__ float warp_reduce(float v) {
    #pragma unroll
    for (int o = 16; o > 0; o >>= 1) v += __shfl_down_sync(0xffffffffu, v, o);
    return v;
}
__device__ __forceinline__ uint32_t smem_u32(const void* p) {
    uint32_t a;
    asm("{ .reg .u64 t; cvta.to.shared.u64 t, %1; cvt.u32.u64 %0, t; }" : "=r"(a) : "l"(p));
    return a;
}
__device__ __forceinline__ void cp_async16(uint32_t s, const void* g) {
    asm volatile("cp.async.cg.shared.global [%0], [%1], 16;" :: "r"(s), "l"(g));
}
__device__ __forceinline__ void cp_commit() {
    asm volatile("cp.async.commit_group;" ::: "memory");
}
template<int NN> __device__ __forceinline__ void cp_wait() {
    asm volatile("cp.async.wait_group %0;" :: "n"(NN) : "memory");
}
__device__ __forceinline__ void ldm_x4(uint32_t* r, uint32_t addr) {
    asm volatile("ldmatrix.sync.aligned.m8n8.x4.shared.b16 {%0,%1,%2,%3}, [%4];"
                 : "=r"(r[0]), "=r"(r[1]), "=r"(r[2]), "=r"(r[3]) : "r"(addr));
}
__device__ __forceinline__ void mma16816(float* d, const uint32_t* a, const uint32_t* b) {
    asm volatile(
        "mma.sync.aligned.m16n8k16.row.col.f32.f16.f16.f32 "
        "{%0,%1,%2,%3}, {%4,%5,%6,%7}, {%8,%9}, {%0,%1,%2,%3};"
        : "+f"(d[0]), "+f"(d[1]), "+f"(d[2]), "+f"(d[3])
        : "r"(a[0]), "r"(a[1]), "r"(a[2]), "r"(a[3]), "r"(b[0]), "r"(b[1]));
}

// ---------------- 0) init ----------------
__global__ void init_kernel() {
    int tid = blockIdx.x * blockDim.x + threadIdx.x;
    if (tid < N_NODES * HEADS) g_denom[tid] = 0.0f;
    if (tid < N_NODES) {
        g_cnt[tid] = 0;
        g_need_out[tid] = 0;
        g_need_h[tid]   = 0;
    }
    if (tid == 0) { g_hcount = 0; g_ucount = 0; }
}

// ---------------- 1) dtype detection ----------------
__global__ void detect_dtype_kernel(const void* edge_index) {
    if (threadIdx.x == 0 && blockIdx.x == 0) {
        const long long* p = (const long long*)edge_index;
        int ok = 1;
        for (int i = 0; i < 64; i++) {
            long long v = p[i];
            if (v < 0 || v >= N_NODES) { ok = 0; break; }
        }
        g_is64 = ok;
    }
}

// ---------------- 2) mark needed output nodes ----------------
__global__ void mark_dst_kernel(const void* __restrict__ si, const void* __restrict__ di) {
    int i = blockIdx.x * blockDim.x + threadIdx.x;
    if (i < BATCH)            g_need_out[load_idx(si, i)] = 1;
    else if (i < 2 * BATCH)   g_need_out[load_idx(di, i - BATCH)] = 1;
}

// ---------------- 3) mark needed h rows ----------------
__global__ void mark_src_kernel(const void* __restrict__ ei) {
    int e = blockIdx.x * blockDim.x + threadIdx.x;
    if (e >= E_EDGES) return;
    int d = load_idx(ei, E_EDGES + e);
    if (g_need_out[d]) {
        int s = load_idx(ei, e);
        g_need_h[s] = 1;
    }
}

// ---------------- 4) compact h list + union list ----------------
__global__ void compact_kernel() {
    int n = blockIdx.x * blockDim.x + threadIdx.x;
    if (n >= N_NODES) return;
    unsigned char nh = g_need_h[n];
    if (nh) {
        int p = atomicAdd(&g_hcount, 1);
        g_hlist[p] = n;
        g_hidx[n] = p;
    }
    if (nh || g_need_out[n]) {
        int p = atomicAdd(&g_ucount, 1);
        g_ulist[p] = n;
    }
}

// ---------------- 5) c vectors ----------------
__global__ void cvec_kernel(const float* __restrict__ Wm,
                            const float* __restrict__ a_src,
                            const float* __restrict__ a_dst) {
    int wid  = (blockIdx.x * blockDim.x + threadIdx.x) >> 5;
    int lane = threadIdx.x & 31;
    if (wid >= IN_DIM * HEADS) return;
    int k = wid >> 2, h = wid & 3;
    const float* wrow = Wm + (size_t)k * HID + h * OUT_DIM;
    const float* as = a_src + h * OUT_DIM;
    const float* ad = a_dst + h * OUT_DIM;
    float cs = 0.f, cd = 0.f;
    for (int d = lane; d < OUT_DIM; d += 32) {
        float w = wrow[d];
        cs = fmaf(w, as[d], cs);
        cd = fmaf(w, ad[d], cd);
    }
    cs = warp_reduce(cs);
    cd = warp_reduce(cd);
    if (lane == 0) { g_csrc[k * 4 + h] = cs; g_cdst[k * 4 + h] = cd; }
}

// ---------------- 6) rel logits ----------------
__global__ void rel_logits_kernel(const float* __restrict__ rel_feat,
                                  const float* __restrict__ a_rel) {
    int wid  = (blockIdx.x * blockDim.x + threadIdx.x) >> 5;
    int lane = threadIdx.x & 31;
    if (wid >= NUM_REL * HEADS) return;
    int r = wid >> 2, h = wid & 3;
    const float* rp = rel_feat + (size_t)r * HID + h * OUT_DIM;
    const float* ar = a_rel + h * OUT_DIM;
    float s = 0.f;
    for (int d = lane; d < OUT_DIM; d += 32) s = fmaf(rp[d], ar[d], s);
    s = warp_reduce(s);
    if (lane == 0) g_rlog[wid] = s;
}

// ---------------- 7) fused split over union list + W transpose ----------------
__global__ void __launch_bounds__(256) split_fused_kernel(const float* __restrict__ A,
                                                          const float* __restrict__ Wm) {
    const int bid = blockIdx.x;
    if (bid < SPLITA_BLOCKS) {
        const int t = threadIdx.x;
        const int lane = t & 31;
        const int ulen = g_ucount;
        float4 cs[4], cd[4];
        #pragma unroll
        for (int q = 0; q < 4; q++) {
            cs[q] = ((const float4*)g_csrc)[t * 4 + q];
            cd[q] = ((const float4*)g_cdst)[t * 4 + q];
        }
        for (int li = bid; li < ulen; li += SPLITA_BLOCKS) {
            const int n = g_ulist[li];
            float4 a = ((const float4*)(A + (size_t)n * IN_DIM))[t];
            float av[4] = {a.x, a.y, a.z, a.w};
            float ss0 = 0.f, ss1 = 0.f, ss2 = 0.f, ss3 = 0.f;
            float sd0 = 0.f, sd1 = 0.f, sd2 = 0.f, sd3 = 0.f;
            #pragma unroll
            for (int q = 0; q < 4; q++) {
                ss0 = fmaf(av[q], cs[q].x, ss0); ss1 = fmaf(av[q], cs[q].y, ss1);
                ss2 = fmaf(av[q], cs[q].z, ss2); ss3 = fmaf(av[q], cs[q].w, ss3);
                sd0 = fmaf(av[q], cd[q].x, sd0); sd1 = fmaf(av[q], cd[q].y, sd1);
                sd2 = fmaf(av[q], cd[q].z, sd2); sd3 = fmaf(av[q], cd[q].w, sd3);
            }
            __half2* ph = (__half2*)(g_Ah + (size_t)n * IN_DIM) + t * 2;
            ph[0] = __halves2half2(__float2half(a.x), __float2half(a.y));
            ph[1] = __halves2half2(__float2half(a.z), __float2half(a.w));
            #pragma unroll
            for (int o = 16; o > 0; o >>= 1) {
                ss0 += __shfl_xor_sync(0xffffffffu, ss0, o);
                ss1 += __shfl_xor_sync(0xffffffffu, ss1, o);
                ss2 += __shfl_xor_sync(0xffffffffu, ss2, o);
                ss3 += __shfl_xor_sync(0xffffffffu, ss3, o);
                sd0 += __shfl_xor_sync(0xffffffffu, sd0, o);
                sd1 += __shfl_xor_sync(0xffffffffu, sd1, o);
                sd2 += __shfl_xor_sync(0xffffffffu, sd2, o);
                sd3 += __shfl_xor_sync(0xffffffffu, sd3, o);
            }
            if (lane == 0) {
                atomicAdd(&g_ssrc[n * 4 + 0], ss0);
                atomicAdd(&g_ssrc[n * 4 + 1], ss1);
                atomicAdd(&g_ssrc[n * 4 + 2], ss2);
                atomicAdd(&g_ssrc[n * 4 + 3], ss3);
                atomicAdd(&g_sdst[n * 4 + 0], sd0);
                atomicAdd(&g_sdst[n * 4 + 1], sd1);
                atomicAdd(&g_sdst[n * 4 + 2], sd2);
                atomicAdd(&g_sdst[n * 4 + 3], sd3);
            }
        }
    } else {
        __shared__ float tile[32][33];
        const int b = bid - SPLITA_BLOCKS;
        const int tx = threadIdx.x & 31;
        const int ty = threadIdx.x >> 5;
        const int k0 = (b % (IN_DIM / 32)) * 32;
        const int n0 = (b / (IN_DIM / 32)) * 32;
        #pragma unroll
        for (int j = 0; j < 4; j++) {
            int k = k0 + ty + j * 8;
            int n = n0 + tx;
            tile[ty + j * 8][tx] = (n < HID) ? Wm[(size_t)k * HID + n] : 0.0f;
        }
        __syncthreads();
        #pragma unroll
        for (int j = 0; j < 4; j++) {
            int n = n0 + ty + j * 8;
            int k = k0 + tx;
            g_Bh[(size_t)n * IN_DIM + k] = __float2half(tile[tx][ty + j * 8]);
        }
    }
}

// note: ssrc/sdst must be zeroed before split (atomicAdd accumulation)
__global__ void zero_s_kernel() {
    int tid = blockIdx.x * blockDim.x + threadIdx.x;
    if (tid < N_NODES * HEADS) { g_ssrc[tid] = 0.0f; g_sdst[tid] = 0.0f; }
}

// ---------------- 8) HMMA GEMM over compacted rows, single fp16 pass ----------------
__global__ void __launch_bounds__(256) gemm_mma_kernel() {
    __shared__ int rowlist[BM];
    const int len = g_hcount;
    const int mt0 = blockIdx.y * BM;
    if (mt0 >= len) return;

    extern __shared__ char smem[];
    const uint32_t sbase = smem_u32(smem);
    const int t = threadIdx.x;
    const int lane = t & 31;
    const int warp = t >> 5;
    const int wm = warp >> 1;
    const int wn = warp & 1;
    const int n0 = blockIdx.x * BN;

    if (t < BM) {
        int rr = mt0 + t;
        rowlist[t] = g_hlist[rr < len ? rr : len - 1];
    }
    __syncthreads();

    float acc[2][4][4];
    #pragma unroll
    for (int mi = 0; mi < 2; mi++)
        #pragma unroll
        for (int nj = 0; nj < 4; nj++)
            #pragma unroll
            for (int q = 0; q < 4; q++) acc[mi][nj][q] = 0.0f;

    auto load_chunk = [&](int c, int buf) {
        // A: 128 rows x 32 k fp16 = 512 16B-slots; 256 threads x 2
        #pragma unroll
        for (int i = 0; i < 2; i++) {
            int lin = i * 256 + t;
            int r = lin >> 2, seg = lin & 3;
            int node = rowlist[r];
            size_t go = (size_t)node * IN_DIM + c * BK + seg * 8;
            uint32_t so = (uint32_t)(r * A_STRIDE + seg * 16);
            cp_async16(sbase + SA_OFF(buf) + so, g_Ah + go);
        }
        {
            int r = t >> 2, seg = t & 3;
            size_t go = (size_t)(n0 + r) * IN_DIM + c * BK + seg * 8;
            uint32_t so = (uint32_t)(r * A_STRIDE + seg * 16);
            cp_async16(sbase + SB_OFF(buf) + so, g_Bh + go);
        }
        cp_commit();
    };

    load_chunk(0, 0);
    load_chunk(1, 1);

    for (int c = 0; c < NCHUNK; c++) {
        if (c == NCHUNK - 1) cp_wait<0>(); else cp_wait<1>();
        __syncthreads();
        const int buf = c & 1;

        #pragma unroll
        for (int k16 = 0; k16 < BK; k16 += 16) {
            uint32_t af[2][4];
            #pragma unroll
            for (int mi = 0; mi < 2; mi++) {
                int r = wm * 32 + mi * 16 + (lane & 7) + ((lane >> 3) & 1) * 8;
                int colB = (k16 + (lane >> 4) * 8) * 2;
                ldm_x4(af[mi], sbase + SA_OFF(buf) + r * A_STRIDE + colB);
            }
            uint32_t bf[4][2];
            #pragma unroll
            for (int pr = 0; pr < 2; pr++) {
                uint32_t r4[4];
                int n = wn * 32 + pr * 16 + ((lane >> 4) & 1) * 8 + (lane & 7);
                int colB = (k16 + ((lane >> 3) & 1) * 8) * 2;
                ldm_x4(r4, sbase + SB_OFF(buf) + n * A_STRIDE + colB);
                bf[pr * 2 + 0][0] = r4[0]; bf[pr * 2 + 0][1] = r4[1];
                bf[pr * 2 + 1][0] = r4[2]; bf[pr * 2 + 1][1] = r4[3];
            }
            #pragma unroll
            for (int mi = 0; mi < 2; mi++)
                #pragma unroll
                for (int nj = 0; nj < 4; nj++)
                    mma16816(acc[mi][nj], af[mi], bf[nj]);
        }
        __syncthreads();
        if (c + 2 < NCHUNK) load_chunk(c + 2, buf);
    }

    #pragma unroll
    for (int mi = 0; mi < 2; mi++)
        #pragma unroll
        for (int nj = 0; nj < 4; nj++) {
            int tileN = n0 + wn * 32 + nj * 8;
            if (tileN >= HID) continue;
            int col = tileN + 2 * (lane & 3);
            int lr0 = wm * 32 + mi * 16 + (lane >> 2);
            if (mt0 + lr0 < len)
                *(float2*)(g_h + (size_t)(mt0 + lr0) * HID + col) =
                    make_float2(acc[mi][nj][0], acc[mi][nj][1]);
            if (mt0 + lr0 + 8 < len)
                *(float2*)(g_h + (size_t)(mt0 + lr0 + 8) * HID + col) =
                    make_float2(acc[mi][nj][2], acc[mi][nj][3]);
        }
}

// ---------------- 9) edge pass (gated) ----------------
__global__ void edge_lse_kernel(const void* __restrict__ ei,
                                const void* __restrict__ et) {
    int idx = blockIdx.x * blockDim.x + threadIdx.x;
    if (idx >= E_EDGES * HEADS) return;
    int e = idx >> 2, h = idx & 3;
    int d = load_idx(ei, E_EDGES + e);
    if (!g_need_out[d]) return;
    int s = load_idx(ei, e);
    int r = load_idx(et, e);
    float x = g_ssrc[s * 4 + h] + g_sdst[d * 4 + h] + g_rlog[r * 4 + h];
    x = (x >= 0.f) ? x : NEG_SLOPE * x;
    float ev = expf(x);
    g_elog[idx] = ev;
    atomicAdd(&g_denom[d * 4 + h], ev);
    if (h == 0) atomicAdd(&g_cnt[d], 1);
}

// ---------------- 10) exclusive scan ----------------
__global__ void scan_kernel() {
    __shared__ int warp_sums[32];
    __shared__ int s_base;
    const int t = threadIdx.x;
    const int lane = t & 31, wid = t >> 5;
    if (t == 0) s_base = 0;
    __syncthreads();
    const int nchunks = (N_NODES + 1023) / 1024;
    for (int ch = 0; ch < nchunks; ch++) {
        int i = ch * 1024 + t;
        int v = (i < N_NODES) ? g_cnt[i] : 0;
        int x = v;
        #pragma unroll
        for (int o = 1; o < 32; o <<= 1) {
            int y = __shfl_up_sync(0xffffffffu, x, o);
            if (lane >= o) x += y;
        }
        if (lane == 31) warp_sums[wid] = x;
        __syncthreads();
        if (wid == 0) {
            int w = warp_sums[lane];
            #pragma unroll
            for (int o = 1; o < 32; o <<= 1) {
                int y = __shfl_up_sync(0xffffffffu, w, o);
                if (lane >= o) w += y;
            }
            warp_sums[lane] = w;
        }
        __syncthreads();
        int warp_off = (wid == 0) ? 0 : warp_sums[wid - 1];
        int excl = s_base + warp_off + (x - v);
        if (i < N_NODES) { g_rowptr[i] = excl; g_cursor[i] = excl; }
        __syncthreads();
        if (t == 0) s_base += warp_sums[31];
        __syncthreads();
    }
    if (t == 0) g_rowptr[N_NODES] = s_base;
}

// ---------------- 11) CSR fill (gated) ----------------
__global__ void fill_kernel(const void* __restrict__ ei) {
    int e = blockIdx.x * blockDim.x + threadIdx.x;
    if (e >= E_EDGES) return;
    int d = load_idx(ei, E_EDGES + e);
    if (!g_need_out[d]) return;
    int pos = atomicAdd(&g_cursor[d], 1);
    g_csre[pos] = e;
}

// ---------------- 12) aggregate (needed nodes, compacted h) ----------------
__global__ void __launch_bounds__(256) agg_kernel(const void* __restrict__ ei) {
    int n    = (blockIdx.x * blockDim.x + threadIdx.x) >> 5;
    int lane = threadIdx.x & 31;
    if (n >= N_NODES) return;
    if (!g_need_out[n]) return;
    int rp0 = g_rowptr[n], rp1 = g_rowptr[n + 1];
    float4 dn = *(const float4*)(g_denom + n * 4);
    float r0 = (rp1 > rp0) ? 1.0f / dn.x : 0.0f;
    float r1 = (rp1 > rp0) ? 1.0f / dn.y : 0.0f;
    float r2 = (rp1 > rp0) ? 1.0f / dn.z : 0.0f;
    float r3 = (rp1 > rp0) ? 1.0f / dn.w : 0.0f;
    float4 acc[7];
    #pragma unroll
    for (int it = 0; it < 7; it++) acc[it] = make_float4(0.f, 0.f, 0.f, 0.f);

    for (int j = rp0; j < rp1; j++) {
        int e = g_csre[j];
        int s = load_idx(ei, e);
        int hrow = g_hidx[s];
        float4 ev = *(const float4*)(g_elog + e * 4);
        float a0 = ev.x * r0, a1 = ev.y * r1, a2 = ev.z * r2, a3 = ev.w * r3;
        const float4* hs = (const float4*)(g_h + (size_t)hrow * HID);
        #pragma unroll
        for (int it = 0; it < 7; it++) {
            int c = lane + it * 32;
            if (c < HID / 4) {
                float a = (c < 50) ? a0 : (c < 100) ? a1 : (c < 150) ? a2 : a3;
                float4 v = hs[c];
                acc[it].x = fmaf(a, v.x, acc[it].x);
                acc[it].y = fmaf(a, v.y, acc[it].y);
                acc[it].z = fmaf(a, v.z, acc[it].z);
                acc[it].w = fmaf(a, v.w, acc[it].w);
            }
        }
    }
    float4* op = (float4*)(g_out + (size_t)n * HID);
    #pragma unroll
    for (int it = 0; it < 7; it++) {
        int c = lane + it * 32;
        if (c < HID / 4) op[c] = acc[it];
    }
}

// ---------------- 13) DistMult ----------------
__global__ void distmult_kernel(const float* __restrict__ bias,
                                const float* __restrict__ rel_emb,
                                const void* __restrict__ si,
                                const void* __restrict__ ri,
                                const void* __restrict__ di,
                                float* __restrict__ out) {
    int wid  = (blockIdx.x * blockDim.x + threadIdx.x) >> 5;
    int lane = threadIdx.x & 31;
    if (wid >= BATCH) return;
    int s = load_idx(si, wid);
    int r = load_idx(ri, wid);
    int d = load_idx(di, wid);
    const float* ps = g_out + (size_t)s * HID;
    const float* pd = g_out + (size_t)d * HID;
    const float* pr = rel_emb + (size_t)r * HID;
    float acc = 0.f;
    for (int k = lane; k < HID; k += 32) {
        float b = bias[k];
        acc = fmaf((ps[k] + b) * pr[k], (pd[k] + b), acc);
    }
    acc = warp_reduce(acc);
    if (lane == 0) out[wid] = acc;
}

// ---------------- launch ----------------
extern "C" void kernel_launch(void* const* d_in, const int* in_sizes, int n_in,
                              void* d_out, int out_size) {
    const float* node_emb   = (const float*)d_in[0];
    const float* Wm         = (const float*)d_in[1];
    const float* bias       = (const float*)d_in[2];
    const float* a_src      = (const float*)d_in[3];
    const float* a_dst      = (const float*)d_in[4];
    const float* a_rel      = (const float*)d_in[5];
    const float* rel_feat   = (const float*)d_in[6];
    const float* rel_emb    = (const float*)d_in[7];
    const void*  edge_index = d_in[8];
    const void*  edge_type  = d_in[9];
    const void*  src_ids    = d_in[10];
    const void*  rel_ids    = d_in[11];
    const void*  dst_ids    = d_in[12];
    float* out = (float*)d_out;

    cudaFuncSetAttribute(gemm_mma_kernel,
                         cudaFuncAttributeMaxDynamicSharedMemorySize, SM_TOT);

    init_kernel<<<(N_NODES * HEADS + 255) / 256, 256>>>();
    zero_s_kernel<<<(N_NODES * HEADS + 255) / 256, 256>>>();
    detect_dtype_kernel<<<1, 32>>>(edge_index);
    mark_dst_kernel<<<(2 * BATCH + 255) / 256, 256>>>(src_ids, dst_ids);
    mark_src_kernel<<<(E_EDGES + 255) / 256, 256>>>(edge_index);
    compact_kernel<<<(N_NODES + 255) / 256, 256>>>();

    cvec_kernel<<<(IN_DIM * HEADS * 32 + 255) / 256, 256>>>(Wm, a_src, a_dst);
    rel_logits_kernel<<<(NUM_REL * HEADS * 32 + 255) / 256, 256>>>(rel_feat, a_rel);

    split_fused_kernel<<<SPLITA_BLOCKS + SPLITB_BLOCKS, 256>>>(node_emb, Wm);

    dim3 ggrid(NT_N, NT_M);
    gemm_mma_kernel<<<ggrid, 256, SM_TOT>>>();

    edge_lse_kernel<<<(E_EDGES * HEADS + 255) / 256, 256>>>(edge_index, edge_type);
    scan_kernel<<<1, 1024>>>();
    fill_kernel<<<(E_EDGES + 255) / 256, 256>>>(edge_index);
    agg_kernel<<<(N_NODES * 32 + 255) / 256, 256>>>(edge_index);

    distmult_kernel<<<(BATCH * 32 + 255) / 256, 256>>>(bias, rel_emb,
                                                       src_ids, rel_ids, dst_ids, out);
}